// round 6
// baseline (speedup 1.0000x reference)
#include <cuda_runtime.h>
#include <cuda_bf16.h>

// Problem constants
#define BB   64
#define LL   32
#define NT   64
#define TT   64
#define SS   128
#define VV   50000
#define EMB  512
#define SD   512
#define EPSF 1e-9f
#define NCELL 528           // L*(L+1)/2 per batch
#define MAXCELLS 1984       // max cells in one level = 64*31

// ----------------------------------------------------------------------------
// Persistent scratch (device globals; static zero-init gives zero upper halves
// of chart_p for levels >= 2, which are never written)
// ----------------------------------------------------------------------------
__device__ float g_chart_p[BB * NCELL * SS];    // 17 MB
__device__ float g_u      [BB * NCELL * SS];    // 17 MB
__device__ float g_chart_f[BB * NCELL * SD];    // 69 MB
__device__ float g_T      [BB * NCELL * 1024];  // 138 MB  (Lt | Rt)
__device__ float g_GsumT  [2][64 * 128];        // GsumT[v][t][s]
__device__ float g_W2     [512 * 1024];         // [k][j] j<512:Wm_top else Wm_bot
__device__ float g_GB1    [64 * 4096];          // GB1[t][a*64+s]  = G[a,s,64+t]
__device__ float g_GB2    [64 * 8192];          // GB2[s][a*128+t] = G[a,64+s,t]
__device__ float g_G2m    [4096 * 64];          // G2m[s*64+t][a]  = G[a,s,t]
__device__ float g_R1     [BB * LL * 4096];     // per len-1 cell: [a*64+s]
__device__ float g_R1L    [BB * LL * 8192];     // per len-1 cell: [a*128+t]
__device__ float g_O      [MAXCELLS * 4096];    // 32.5 MB, one level at a time
__device__ float g_scAB   [MAXCELLS * 64];
__device__ float g_scMid  [MAXCELLS * 64];

__host__ __device__ __forceinline__ int triOff(int len) {
    return ((len - 1) * (66 - len)) >> 1;
}
__device__ __forceinline__ int cellIdx(int b, int i, int len) {
    return b * NCELL + triOff(len) + i;
}

// ----------------------------------------------------------------------------
// Prep kernels
// ----------------------------------------------------------------------------
__global__ void build_gsum(const float* __restrict__ G) {
    int idx = blockIdx.x * 256 + threadIdx.x;           // 2*64*128
    if (idx >= 2 * 64 * 128) return;
    int v = idx >> 13, t = (idx >> 7) & 63, s = idx & 127;
    const float* gp = G + s * 128 + v * 64 + t;
    float sum = 0.f;
    #pragma unroll 8
    for (int a = 0; a < 64; ++a) sum += gp[a * 16384];
    g_GsumT[v][t * 128 + s] = sum;
}

__global__ void build_w2(const float* __restrict__ Wm) {
    int idx = blockIdx.x * 256 + threadIdx.x;           // 512*1024
    if (idx >= 512 * 1024) return;
    int k = idx >> 10, j = idx & 1023;
    g_W2[idx] = (j < 512) ? Wm[k * 512 + j] : Wm[(512 + k) * 512 + (j - 512)];
}

__global__ void build_gb1(const float* __restrict__ G) {
    int idx = blockIdx.x * 256 + threadIdx.x;           // 64*4096
    if (idx >= 64 * 4096) return;
    int t = idx >> 12, j = idx & 4095;
    int a = j >> 6, s = j & 63;
    g_GB1[idx] = G[a * 16384 + s * 128 + 64 + t];
}

__global__ void build_gb2(const float* __restrict__ G) {
    int idx = blockIdx.x * 256 + threadIdx.x;           // 64*8192
    if (idx >= 64 * 8192) return;
    int s = idx >> 13, j = idx & 8191;
    int a = j >> 7, t = j & 127;
    g_GB2[idx] = G[a * 16384 + (64 + s) * 128 + t];
}

__global__ void build_g2m(const float* __restrict__ G) {
    int idx = blockIdx.x * 256 + threadIdx.x;           // 4096*64
    if (idx >= 4096 * 64) return;
    int st = idx >> 6, a = idx & 63;
    int s = st >> 6, t = st & 63;
    g_G2m[idx] = G[a * 16384 + s * 128 + t];
}

// ----------------------------------------------------------------------------
// Level-1 preterminal distribution
// ----------------------------------------------------------------------------
__global__ void diag_kernel(const int* __restrict__ word,
                            const float* __restrict__ preterm) {
    int c = blockIdx.x;                  // b*32+i
    int tid = threadIdx.x;               // 64 threads
    int w = word[c];
    float v = preterm[tid * VV + w];
    float s = v;
    #pragma unroll
    for (int o = 16; o; o >>= 1) s += __shfl_down_sync(0xffffffffu, s, o);
    __shared__ float red[2];
    if ((tid & 31) == 0) red[tid >> 5] = s;
    __syncthreads();
    float tot = red[0] + red[1] + EPSF;
    int b = c >> 5, i = c & 31;
    float* cp = g_chart_p + (long)cellIdx(b, i, 1) * SS;
    cp[tid]      = 0.f;
    cp[64 + tid] = v / tot;
}

// ----------------------------------------------------------------------------
// Generic tiled GEMM (round-4 proven): C[r][j] = sum_k A[r][k]*B[k][j]
// 64x64 tile, BK=16, 256 threads, 4x4 micro-tile; optional gather/bias+relu.
// ----------------------------------------------------------------------------
__global__ void __launch_bounds__(256) gemm_k(
    const float* __restrict__ A, const float* __restrict__ Bm,
    float* __restrict__ C, int K, int N, int n,
    const int* __restrict__ gidx,
    int a_bs, int a_is, int a_cst,
    int c_bs, int c_is, int c_cst,
    const float* __restrict__ bias)
{
    __shared__ float As[16][64];
    __shared__ float Bs[16][64];
    int tid  = threadIdx.x;
    int row0 = blockIdx.y << 6, col0 = blockIdx.x << 6;

    int lr = tid >> 2, lk4 = (tid & 3) << 2;
    int r = row0 + lr;
    const float* Aptr;
    if (gidx) {
        Aptr = A + (long)gidx[r] * EMB + lk4;
    } else {
        int b = r / n, i = r - b * n;
        Aptr = A + (long)b * a_bs + (long)i * a_is + a_cst + lk4;
    }
    int bk = tid >> 4, bn4 = (tid & 15) << 2;
    const float* Bptr = Bm + (long)bk * N + col0 + bn4;

    int ty = tid >> 4, tx = tid & 15;
    float acc[4][4];
    #pragma unroll
    for (int ii = 0; ii < 4; ++ii)
        #pragma unroll
        for (int jj = 0; jj < 4; ++jj) acc[ii][jj] = 0.f;

    for (int k0 = 0; k0 < K; k0 += 16) {
        float4 av = *(const float4*)(Aptr + k0);
        float4 bv = *(const float4*)(Bptr + (long)k0 * N);
        if (k0) __syncthreads();
        As[lk4 + 0][lr] = av.x; As[lk4 + 1][lr] = av.y;
        As[lk4 + 2][lr] = av.z; As[lk4 + 3][lr] = av.w;
        *(float4*)&Bs[bk][bn4] = bv;
        __syncthreads();
        #pragma unroll
        for (int kk = 0; kk < 16; ++kk) {
            float4 af = *(const float4*)&As[kk][ty << 2];
            float4 bf = *(const float4*)&Bs[kk][tx << 2];
            float ar[4] = {af.x, af.y, af.z, af.w};
            float br[4] = {bf.x, bf.y, bf.z, bf.w};
            #pragma unroll
            for (int ii = 0; ii < 4; ++ii)
                #pragma unroll
                for (int jj = 0; jj < 4; ++jj)
                    acc[ii][jj] += ar[ii] * br[jj];
        }
    }

    int cc = col0 + (tx << 2);
    #pragma unroll
    for (int ii = 0; ii < 4; ++ii) {
        int rr = row0 + (ty << 2) + ii;
        int b = rr / n, i = rr - b * n;
        float* Cp = C + (long)b * c_bs + (long)i * c_is + c_cst + cc;
        float4 v = make_float4(acc[ii][0], acc[ii][1], acc[ii][2], acc[ii][3]);
        if (bias) {
            v.x = fmaxf(v.x + bias[cc + 0], 0.f);
            v.y = fmaxf(v.y + bias[cc + 1], 0.f);
            v.z = fmaxf(v.z + bias[cc + 2], 0.f);
            v.w = fmaxf(v.w + bias[cc + 3], 0.f);
        }
        *(float4*)Cp = v;
    }
}

// ----------------------------------------------------------------------------
// Fused level kernel: masses (via u), boundary-split scores via R1/R1L dots,
// middle-split outer-product accumulation (registers) -> g_O, weighted combine.
// One block of 256 threads per parent cell.
// ----------------------------------------------------------------------------
__device__ __forceinline__ float dot16g(const float* __restrict__ g,
                                        const float* s) {
    float4 v0 = ((const float4*)g)[0];
    float4 v1 = ((const float4*)g)[1];
    float4 v2 = ((const float4*)g)[2];
    float4 v3 = ((const float4*)g)[3];
    return v0.x*s[0] + v0.y*s[1] + v0.z*s[2] + v0.w*s[3]
         + v1.x*s[4] + v1.y*s[5] + v1.z*s[6] + v1.w*s[7]
         + v2.x*s[8] + v2.y*s[9] + v2.z*s[10] + v2.w*s[11]
         + v3.x*s[12] + v3.y*s[13] + v3.z*s[14] + v3.w*s[15];
}

__global__ void __launch_bounds__(256) level_kernel(int ln, int n,
                                                    const float* __restrict__ bm) {
    int c = blockIdx.x;
    int b = c / n, i = c - b * n;
    int tid = threadIdx.x;
    int a = tid >> 2, q = tid & 3;      // a in [0,64), quarter q
    int t0 = q << 4;
    __shared__ float lp[64], rp[64], us[64], red[2], sc[64], massS[32];

    float Oacc[16];
    #pragma unroll
    for (int j = 0; j < 16; ++j) Oacc[j] = 0.f;
    float accAB = 0.f;

    for (int d = 1; d < ln; ++d) {
        int soff = (d == 1) ? 64 : 0;
        int rLen = ln - d;
        int soff_r = (rLen == 1) ? 64 : 0;
        __syncthreads();
        if (tid < 64)
            lp[tid] = g_chart_p[(long)cellIdx(b, i, d) * SS + soff + tid];
        else if (tid < 128)
            us[tid - 64] = g_u[(long)cellIdx(b, i + d, rLen) * SS + soff + (tid - 64)];
        else if (tid < 192)
            rp[tid - 128] = g_chart_p[(long)cellIdx(b, i + d, rLen) * SS + soff_r + (tid - 128)];
        __syncthreads();

        // mass_d = dot(lp, u_right)
        if (tid < 64) {
            float m = lp[tid] * us[tid];
            #pragma unroll
            for (int o = 16; o; o >>= 1) m += __shfl_down_sync(0xffffffffu, m, o);
            if ((tid & 31) == 0) red[tid >> 5] = m;
        }

        if (d == 1) {
            // boundary A: left child is len-1; use R1L[left]
            const float* Rrow = g_R1L + ((long)(b * LL + i)) * 8192
                                      + a * 128 + soff_r + t0;
            accAB += dot16g(Rrow, rp + t0);
        } else if (rLen == 1) {
            // boundary B: right child is len-1; use R1[right]
            const float* Rrow = g_R1 + ((long)(b * LL + i + d)) * 4096
                                     + a * 64 + t0;
            accAB += dot16g(Rrow, lp + t0);
        } else {
            // middle split: accumulate outer product O[s=a][t0..t0+15]
            float l = lp[a];
            #pragma unroll
            for (int j = 0; j < 16; ++j) Oacc[j] += l * rp[t0 + j];
        }
        __syncthreads();
        if (tid == 0) massS[d - 1] = red[0] + red[1];
    }

    // reduce boundary scores over q
    accAB += __shfl_down_sync(0xffffffffu, accAB, 2);
    accAB += __shfl_down_sync(0xffffffffu, accAB, 1);
    if (q == 0) sc[a] = accAB;
    __syncthreads();
    if (tid < 64) g_scAB[c * 64 + tid] = sc[tid];

    // store O_sum for the mid GEMM (only exists for ln >= 4)
    if (ln >= 4) {
        float* Orow = g_O + (long)c * 4096 + a * 64 + t0;
        ((float4*)Orow)[0] = make_float4(Oacc[0],  Oacc[1],  Oacc[2],  Oacc[3]);
        ((float4*)Orow)[1] = make_float4(Oacc[4],  Oacc[5],  Oacc[6],  Oacc[7]);
        ((float4*)Orow)[2] = make_float4(Oacc[8],  Oacc[9],  Oacc[10], Oacc[11]);
        ((float4*)Orow)[3] = make_float4(Oacc[12], Oacc[13], Oacc[14], Oacc[15]);
    }

    // ---- combine phase ----
    int D = ln - 1;
    __shared__ float tot_s;
    if (tid == 0) {
        float t = 0.f;
        for (int d = 0; d < D; ++d) t += massS[d];
        tot_s = t + EPSF;
    }
    __syncthreads();
    float bm0 = bm[tid], bm1 = bm[tid + 256];
    float f0 = 0.f, f1 = 0.f;
    for (int d = 1; d <= D; ++d) {
        const float* TL = g_T + (long)cellIdx(b, i, d) * 1024;
        const float* TR = g_T + (long)cellIdx(b, i + d, ln - d) * 1024 + 512;
        float wd = massS[d - 1] / tot_s;
        f0 += wd * fmaxf(TL[tid]       + TR[tid]       + bm0, 0.f);
        f1 += wd * fmaxf(TL[tid + 256] + TR[tid + 256] + bm1, 0.f);
    }
    float* cf = g_chart_f + (long)cellIdx(b, i, ln) * SD;
    cf[tid]       = f0;
    cf[tid + 256] = f1;
}

// ----------------------------------------------------------------------------
// Normalize: p = (scAB + scMid) / sum, write chart_p NT half
// ----------------------------------------------------------------------------
__global__ void norm_kernel(int ln, int n, int useMid) {
    int c = blockIdx.x;
    int b = c / n, i = c - b * n;
    int tid = threadIdx.x;               // 64 threads
    float v = g_scAB[c * 64 + tid];
    if (useMid) v += g_scMid[c * 64 + tid];
    float s = v;
    #pragma unroll
    for (int o = 16; o; o >>= 1) s += __shfl_down_sync(0xffffffffu, s, o);
    __shared__ float red[2];
    if ((tid & 31) == 0) red[tid >> 5] = s;
    __syncthreads();
    float tot = red[0] + red[1] + EPSF;
    g_chart_p[(long)cellIdx(b, i, ln) * SS + tid] = v / tot;
}

// ----------------------------------------------------------------------------
// Root: out[b,:] = chart_f[b,0,L] * dot(chart_p[b,0,L], starts)
// ----------------------------------------------------------------------------
__global__ void root_kernel(const float* __restrict__ starts, float* __restrict__ out) {
    int b = blockIdx.x, tid = threadIdx.x;  // 128 threads
    const float* p = g_chart_p + (long)cellIdx(b, 0, LL) * SS;
    float v = p[tid] * starts[tid];
    #pragma unroll
    for (int o = 16; o; o >>= 1) v += __shfl_down_sync(0xffffffffu, v, o);
    __shared__ float red[4];
    if ((tid & 31) == 0) red[tid >> 5] = v;
    __syncthreads();
    float score = red[0] + red[1] + red[2] + red[3];
    const float* f = g_chart_f + (long)cellIdx(b, 0, LL) * SD;
    for (int h = tid; h < SD; h += 128) out[b * SD + h] = f[h] * score;
}

// ----------------------------------------------------------------------------
// Host driver
// ----------------------------------------------------------------------------
extern "C" void kernel_launch(void* const* d_in, const int* in_sizes, int n_in,
                              void* d_out, int out_size) {
    const int*   word    = (const int*)  d_in[0];
    const float* emb     = (const float*)d_in[1];
    const float* preterm = (const float*)d_in[2];
    const float* G       = (const float*)d_in[3];
    const float* starts  = (const float*)d_in[4];
    const float* Wp      = (const float*)d_in[5];
    const float* bp      = (const float*)d_in[6];
    const float* Wm      = (const float*)d_in[7];
    const float* bm      = (const float*)d_in[8];
    float* out = (float*)d_out;

    float *pP, *pU, *pF, *pT, *pGsumT, *pW2, *pGB1, *pGB2, *pG2m;
    float *pR1, *pR1L, *pO, *pSab, *pSmid;
    cudaGetSymbolAddress((void**)&pP,     g_chart_p);
    cudaGetSymbolAddress((void**)&pU,     g_u);
    cudaGetSymbolAddress((void**)&pF,     g_chart_f);
    cudaGetSymbolAddress((void**)&pT,     g_T);
    cudaGetSymbolAddress((void**)&pGsumT, g_GsumT);
    cudaGetSymbolAddress((void**)&pW2,    g_W2);
    cudaGetSymbolAddress((void**)&pGB1,   g_GB1);
    cudaGetSymbolAddress((void**)&pGB2,   g_GB2);
    cudaGetSymbolAddress((void**)&pG2m,   g_G2m);
    cudaGetSymbolAddress((void**)&pR1,    g_R1);
    cudaGetSymbolAddress((void**)&pR1L,   g_R1L);
    cudaGetSymbolAddress((void**)&pO,     g_O);
    cudaGetSymbolAddress((void**)&pSab,   g_scAB);
    cudaGetSymbolAddress((void**)&pSmid,  g_scMid);

    // Prep
    build_gsum<<<(2 * 64 * 128 + 255) / 256, 256>>>(G);
    build_w2  <<<(512 * 1024 + 255) / 256, 256>>>(Wm);
    build_gb1 <<<(64 * 4096 + 255) / 256, 256>>>(G);
    build_gb2 <<<(64 * 8192 + 255) / 256, 256>>>(G);
    build_g2m <<<(4096 * 64 + 255) / 256, 256>>>(G);

    // Level 1
    diag_kernel<<<BB * LL, 64>>>(word, preterm);

    {
        int rows = BB * LL;
        // feat0 = relu(emb[word] @ Wp + bp)
        dim3 gF(SD >> 6, rows >> 6);
        gemm_k<<<gF, 256>>>(emb, Wp, pF, EMB, SD, LL, word,
                            0, 0, 0,
                            NCELL * SD, SD, triOff(1) * SD, bp);
        // u for level-1 cells (t active in [64,128))
        dim3 gU(128 >> 6, rows >> 6);
        gemm_k<<<gU, 256>>>(pP, pGsumT[0] ? pGsumT : pGsumT, pU, 64, 128, LL, nullptr,
                            NCELL * SS, SS, triOff(1) * SS + 64,
                            NCELL * SS, SS, triOff(1) * SS, nullptr);
        // fix: second GsumT half (v=1)
        // (overwrite with correct B below)
        gemm_k<<<gU, 256>>>(pP, pGsumT + 64 * 128, pU, 64, 128, LL, nullptr,
                            NCELL * SS, SS, triOff(1) * SS + 64,
                            NCELL * SS, SS, triOff(1) * SS, nullptr);
        // T transform for level-1 cells
        dim3 gT(1024 >> 6, rows >> 6);
        gemm_k<<<gT, 256>>>(pF, pW2, pT, SD, 1024, LL, nullptr,
                            NCELL * SD, SD, triOff(1) * SD,
                            NCELL * 1024, 1024, triOff(1) * 1024, nullptr);
        // R1: [2048 x 4096] = p1 @ GB1
        dim3 gR1(4096 >> 6, rows >> 6);
        gemm_k<<<gR1, 256>>>(pP, pGB1, pR1, 64, 4096, LL, nullptr,
                             NCELL * SS, SS, triOff(1) * SS + 64,
                             LL * 4096, 4096, 0, nullptr);
        // R1L: [2048 x 8192] = p1 @ GB2
        dim3 gR1L(8192 >> 6, rows >> 6);
        gemm_k<<<gR1L, 256>>>(pP, pGB2, pR1L, 64, 8192, LL, nullptr,
                              NCELL * SS, SS, triOff(1) * SS + 64,
                              LL * 8192, 8192, 0, nullptr);
    }

    // Levels 2..32
    for (int ln = 2; ln <= LL; ++ln) {
        int nn = LL - ln + 1;
        int cells = BB * nn;
        level_kernel<<<cells, 256>>>(ln, nn, bm);
        int useMid = (ln >= 4);
        if (useMid) {
            // scMid[cells x 64] = O[cells x 4096] @ G2m[4096 x 64]
            dim3 gM(1, cells >> 6);
            gemm_k<<<gM, 256>>>(pO, pG2m, pSmid, 4096, 64, cells, nullptr,
                                0, 4096, 0,
                                0, 64, 0, nullptr);
        }
        norm_kernel<<<cells, 64>>>(ln, nn, useMid);
        if (ln < LL) {
            // u for this level (active half [0,64))
            dim3 gU(128 >> 6, cells >> 6);
            gemm_k<<<gU, 256>>>(pP, pGsumT, pU, 64, 128, nn, nullptr,
                                NCELL * SS, SS, triOff(ln) * SS,
                                NCELL * SS, SS, triOff(ln) * SS, nullptr);
            // T transform for this level
            dim3 gT(1024 >> 6, cells >> 6);
            gemm_k<<<gT, 256>>>(pF, pW2, pT, SD, 1024, nn, nullptr,
                                NCELL * SD, SD, triOff(ln) * SD,
                                NCELL * 1024, 1024, triOff(ln) * 1024, nullptr);
        }
    }

    // Root
    root_kernel<<<BB, 128>>>(starts, out);
}

// round 9
// speedup vs baseline: 2.5315x; 2.5315x over previous
#include <cuda_runtime.h>
#include <cuda_bf16.h>

// Problem constants
#define BB   64
#define LL   32
#define NT   64
#define TT   64
#define SS   128
#define VV   50000
#define EMB  512
#define SD   512
#define EPSF 1e-9f
#define NCELL 528           // L*(L+1)/2 per batch

// ----------------------------------------------------------------------------
// Persistent scratch (device globals). Static zero-init gives zero upper halves
// of chart_p for levels >= 2 (never written) -> deterministic across replays.
// ----------------------------------------------------------------------------
__device__ float         g_chart_p[BB * NCELL * SS];    // 17 MB
__device__ float         g_u      [BB * NCELL * SS];    // 17 MB
__device__ float         g_chart_f[BB * NCELL * SD];    // 69 MB
__device__ float         g_T      [BB * NCELL * 1024];  // 138 MB  (Lt | Rt)
__device__ __nv_bfloat16 g_Rb     [BB * NCELL * 4096];  // 277 MB  R[c][a*64+s], s<64
__device__ __nv_bfloat16 g_R1L    [BB * LL * 8192];     // 33 MB   R1L[c1][a*128+t]
__device__ float         g_GT     [2][64 * 4096];       // GT[v][t][(a,s)] s<64
__device__ float         g_GB2    [64 * 8192];          // GB2[s][a*128+t] = G[a,64+s,t]
__device__ float         g_GsumT  [2][64 * 128];        // GsumT[v][t][s]
__device__ float         g_W2     [512 * 1024];         // j<512: Wm_top, else Wm_bot

__host__ __device__ __forceinline__ int triOff(int len) {
    return ((len - 1) * (66 - len)) >> 1;
}
__device__ __forceinline__ int cellIdx(int b, int i, int len) {
    return b * NCELL + triOff(len) + i;
}

// ----------------------------------------------------------------------------
// Prep kernels
// ----------------------------------------------------------------------------
__global__ void build_gt(const float* __restrict__ G) {
    int idx = blockIdx.x * 256 + threadIdx.x;           // 64*4096
    if (idx >= 64 * 4096) return;
    int t = idx >> 12, j = idx & 4095;
    int a = j >> 6, s = j & 63;
    const float* gp = G + a * 16384 + s * 128 + t;
    g_GT[0][idx] = gp[0];    // t in [0,64)
    g_GT[1][idx] = gp[64];   // t in [64,128)
}

__global__ void build_gb2(const float* __restrict__ G) {
    int idx = blockIdx.x * 256 + threadIdx.x;           // 64*8192
    if (idx >= 64 * 8192) return;
    int s = idx >> 13, j = idx & 8191;
    int a = j >> 7, t = j & 127;
    g_GB2[idx] = G[a * 16384 + (64 + s) * 128 + t];
}

__global__ void build_gsum(const float* __restrict__ G) {
    int idx = blockIdx.x * 256 + threadIdx.x;           // 2*64*128
    if (idx >= 2 * 64 * 128) return;
    int v = idx >> 13, t = (idx >> 7) & 63, s = idx & 127;
    const float* gp = G + s * 128 + v * 64 + t;
    float sum = 0.f;
    #pragma unroll 8
    for (int a = 0; a < 64; ++a) sum += gp[a * 16384];
    g_GsumT[v][t * 128 + s] = sum;
}

__global__ void build_w2(const float* __restrict__ Wm) {
    int idx = blockIdx.x * 256 + threadIdx.x;           // 512*1024
    if (idx >= 512 * 1024) return;
    int k = idx >> 10, j = idx & 1023;
    g_W2[idx] = (j < 512) ? Wm[k * 512 + j] : Wm[(512 + k) * 512 + (j - 512)];
}

// ----------------------------------------------------------------------------
// Level-1 preterminal distribution
// ----------------------------------------------------------------------------
__global__ void diag_kernel(const int* __restrict__ word,
                            const float* __restrict__ preterm) {
    int c = blockIdx.x;                  // b*32+i
    int tid = threadIdx.x;               // 64 threads
    int w = word[c];
    float v = preterm[tid * VV + w];
    float s = v;
    #pragma unroll
    for (int o = 16; o; o >>= 1) s += __shfl_down_sync(0xffffffffu, s, o);
    __shared__ float red[2];
    if ((tid & 31) == 0) red[tid >> 5] = s;
    __syncthreads();
    float tot = red[0] + red[1] + EPSF;
    int b = c >> 5, i = c & 31;
    float* cp = g_chart_p + (long)cellIdx(b, i, 1) * SS;
    cp[tid]      = 0.f;
    cp[64 + tid] = v / tot;
}

// ----------------------------------------------------------------------------
// Tiled GEMM (round-4 proven): C[r][j] = sum_k A[r][k]*B[k][j]
// 64x64 tile, BK=16, 256 threads, 4x4 micro-tile.
// Options: row gather (gidx), bias+relu, bf16 output.
// ----------------------------------------------------------------------------
__global__ void __launch_bounds__(256) gemm_k(
    const float* __restrict__ A, const float* __restrict__ Bm,
    void* __restrict__ C, int K, int N, int n,
    const int* __restrict__ gidx,
    int a_bs, int a_is, int a_cst,
    long c_bs, int c_is, int c_cst,
    const float* __restrict__ bias, int obf16)
{
    __shared__ float As[16][64];
    __shared__ float Bs[16][64];
    int tid  = threadIdx.x;
    int row0 = blockIdx.y << 6, col0 = blockIdx.x << 6;

    int lr = tid >> 2, lk4 = (tid & 3) << 2;
    int r = row0 + lr;
    const float* Aptr;
    if (gidx) {
        Aptr = A + (long)gidx[r] * EMB + lk4;
    } else {
        int b = r / n, i = r - b * n;
        Aptr = A + (long)b * a_bs + (long)i * a_is + a_cst + lk4;
    }
    int bk = tid >> 4, bn4 = (tid & 15) << 2;
    const float* Bptr = Bm + (long)bk * N + col0 + bn4;

    int ty = tid >> 4, tx = tid & 15;
    float acc[4][4];
    #pragma unroll
    for (int ii = 0; ii < 4; ++ii)
        #pragma unroll
        for (int jj = 0; jj < 4; ++jj) acc[ii][jj] = 0.f;

    for (int k0 = 0; k0 < K; k0 += 16) {
        float4 av = *(const float4*)(Aptr + k0);
        float4 bv = *(const float4*)(Bptr + (long)k0 * N);
        if (k0) __syncthreads();
        As[lk4 + 0][lr] = av.x; As[lk4 + 1][lr] = av.y;
        As[lk4 + 2][lr] = av.z; As[lk4 + 3][lr] = av.w;
        *(float4*)&Bs[bk][bn4] = bv;
        __syncthreads();
        #pragma unroll
        for (int kk = 0; kk < 16; ++kk) {
            float4 af = *(const float4*)&As[kk][ty << 2];
            float4 bf = *(const float4*)&Bs[kk][tx << 2];
            float ar[4] = {af.x, af.y, af.z, af.w};
            float br[4] = {bf.x, bf.y, bf.z, bf.w};
            #pragma unroll
            for (int ii = 0; ii < 4; ++ii)
                #pragma unroll
                for (int jj = 0; jj < 4; ++jj)
                    acc[ii][jj] += ar[ii] * br[jj];
        }
    }

    int cc = col0 + (tx << 2);
    #pragma unroll
    for (int ii = 0; ii < 4; ++ii) {
        int rr = row0 + (ty << 2) + ii;
        int b = rr / n, i = rr - b * n;
        long base = (long)b * c_bs + (long)i * c_is + c_cst + cc;
        float v0 = acc[ii][0], v1 = acc[ii][1], v2 = acc[ii][2], v3 = acc[ii][3];
        if (bias) {
            v0 = fmaxf(v0 + bias[cc + 0], 0.f);
            v1 = fmaxf(v1 + bias[cc + 1], 0.f);
            v2 = fmaxf(v2 + bias[cc + 2], 0.f);
            v3 = fmaxf(v3 + bias[cc + 3], 0.f);
        }
        if (obf16) {
            __nv_bfloat162 h0 = __floats2bfloat162_rn(v0, v1);
            __nv_bfloat162 h1 = __floats2bfloat162_rn(v2, v3);
            uint2 pk = make_uint2(*(unsigned*)&h0, *(unsigned*)&h1);
            *(uint2*)((__nv_bfloat16*)C + base) = pk;
        } else {
            *(float4*)((float*)C + base) = make_float4(v0, v1, v2, v3);
        }
    }
}

// ----------------------------------------------------------------------------
// Fused per-level kernel: scores + masses -> normalize p -> feature combine.
// One block of 256 threads per parent cell.
//   d == 1 : scores[a] += dot_t(rp, R1L[left][a*128+soff_r+t])
//   d >= 2 : scores[a] += dot_s(lp, Rb [right][a*64+s])     (s in [0,64))
// ----------------------------------------------------------------------------
__device__ __forceinline__ float dot16bf(const __nv_bfloat16* __restrict__ r,
                                         const float* s) {
    uint4 v0 = *(const uint4*)r;
    uint4 v1 = *(const uint4*)(r + 8);
    const unsigned* u0 = (const unsigned*)&v0;
    const unsigned* u1 = (const unsigned*)&v1;
    float acc = 0.f;
    #pragma unroll
    for (int w = 0; w < 4; ++w) {
        float2 f0 = __bfloat1622float2(*(const __nv_bfloat162*)&u0[w]);
        float2 f1 = __bfloat1622float2(*(const __nv_bfloat162*)&u1[w]);
        acc += f0.x * s[2 * w]     + f0.y * s[2 * w + 1]
             + f1.x * s[8 + 2 * w] + f1.y * s[8 + 2 * w + 1];
    }
    return acc;
}

__global__ void __launch_bounds__(256) level_kernel(int ln, int n,
                                                    const float* __restrict__ bm) {
    int c = blockIdx.x;
    int b = c / n, i = c - b * n;
    int tid = threadIdx.x;
    int a = tid >> 2, q = tid & 3;      // a in [0,64), quarter q
    int t0 = q << 4;
    __shared__ float lp[64], rp[64], us[64], red[2], sc[64], massS[32];
    float acc = 0.f;

    for (int d = 1; d < ln; ++d) {
        int soff = (d == 1) ? 64 : 0;
        int rLen = ln - d;
        int soff_r = (rLen == 1) ? 64 : 0;
        __syncthreads();
        if (tid < 64)
            lp[tid] = g_chart_p[(long)cellIdx(b, i, d) * SS + soff + tid];
        else if (tid < 128)
            us[tid - 64] = g_u[(long)cellIdx(b, i + d, rLen) * SS + soff + (tid - 64)];
        else if (tid < 192)
            rp[tid - 128] = g_chart_p[(long)cellIdx(b, i + d, rLen) * SS + soff_r + (tid - 128)];
        __syncthreads();

        // mass_d = dot(lp, u_right)
        if (tid < 64) {
            float m = lp[tid] * us[tid];
            #pragma unroll
            for (int o = 16; o; o >>= 1) m += __shfl_down_sync(0xffffffffu, m, o);
            if ((tid & 31) == 0) red[tid >> 5] = m;
        }

        if (d == 1) {
            const __nv_bfloat16* Rrow = g_R1L + ((long)(b * LL + i)) * 8192
                                             + a * 128 + soff_r + t0;
            acc += dot16bf(Rrow, rp + t0);
        } else {
            const __nv_bfloat16* Rrow = g_Rb + (long)cellIdx(b, i + d, rLen) * 4096
                                            + a * 64 + t0;
            acc += dot16bf(Rrow, lp + t0);
        }
        __syncthreads();
        if (tid == 0) massS[d - 1] = red[0] + red[1];
    }

    // reduce scores over q, normalize, write p
    acc += __shfl_down_sync(0xffffffffu, acc, 2);
    acc += __shfl_down_sync(0xffffffffu, acc, 1);
    if (q == 0) sc[a] = acc;
    __syncthreads();
    if (tid < 64) {
        float v = sc[tid];
        #pragma unroll
        for (int o = 16; o; o >>= 1) v += __shfl_down_sync(0xffffffffu, v, o);
        if ((tid & 31) == 0) red[tid >> 5] = v;
    }
    __syncthreads();
    float ptot = red[0] + red[1] + EPSF;
    if (tid < 64)
        g_chart_p[(long)cellIdx(b, i, ln) * SS + tid] = sc[tid] / ptot;

    // ---- combine phase ----
    int D = ln - 1;
    __shared__ float tot_s;
    if (tid == 0) {
        float t = 0.f;
        for (int d = 0; d < D; ++d) t += massS[d];
        tot_s = t + EPSF;
    }
    __syncthreads();
    float bm0 = bm[tid], bm1 = bm[tid + 256];
    float f0 = 0.f, f1 = 0.f;
    for (int d = 1; d <= D; ++d) {
        const float* TL = g_T + (long)cellIdx(b, i, d) * 1024;
        const float* TR = g_T + (long)cellIdx(b, i + d, ln - d) * 1024 + 512;
        float wd = massS[d - 1] / tot_s;
        f0 += wd * fmaxf(TL[tid]       + TR[tid]       + bm0, 0.f);
        f1 += wd * fmaxf(TL[tid + 256] + TR[tid + 256] + bm1, 0.f);
    }
    float* cf = g_chart_f + (long)cellIdx(b, i, ln) * SD;
    cf[tid]       = f0;
    cf[tid + 256] = f1;
}

// ----------------------------------------------------------------------------
// Root: out[b,:] = chart_f[b,0,L] * dot(chart_p[b,0,L], starts)
// ----------------------------------------------------------------------------
__global__ void root_kernel(const float* __restrict__ starts, float* __restrict__ out) {
    int b = blockIdx.x, tid = threadIdx.x;  // 128 threads
    const float* p = g_chart_p + (long)cellIdx(b, 0, LL) * SS;
    float v = p[tid] * starts[tid];
    #pragma unroll
    for (int o = 16; o; o >>= 1) v += __shfl_down_sync(0xffffffffu, v, o);
    __shared__ float red[4];
    if ((tid & 31) == 0) red[tid >> 5] = v;
    __syncthreads();
    float score = red[0] + red[1] + red[2] + red[3];
    const float* f = g_chart_f + (long)cellIdx(b, 0, LL) * SD;
    for (int h = tid; h < SD; h += 128) out[b * SD + h] = f[h] * score;
}

// ----------------------------------------------------------------------------
// Host driver
// ----------------------------------------------------------------------------
extern "C" void kernel_launch(void* const* d_in, const int* in_sizes, int n_in,
                              void* d_out, int out_size) {
    const int*   word    = (const int*)  d_in[0];
    const float* emb     = (const float*)d_in[1];
    const float* preterm = (const float*)d_in[2];
    const float* G       = (const float*)d_in[3];
    const float* starts  = (const float*)d_in[4];
    const float* Wp      = (const float*)d_in[5];
    const float* bp      = (const float*)d_in[6];
    const float* Wm      = (const float*)d_in[7];
    const float* bm      = (const float*)d_in[8];
    float* out = (float*)d_out;

    float *pP, *pU, *pF, *pT, *pGT, *pGB2, *pGsumT, *pW2;
    __nv_bfloat16 *pRb, *pR1L;
    cudaGetSymbolAddress((void**)&pP,     g_chart_p);
    cudaGetSymbolAddress((void**)&pU,     g_u);
    cudaGetSymbolAddress((void**)&pF,     g_chart_f);
    cudaGetSymbolAddress((void**)&pT,     g_T);
    cudaGetSymbolAddress((void**)&pRb,    g_Rb);
    cudaGetSymbolAddress((void**)&pR1L,   g_R1L);
    cudaGetSymbolAddress((void**)&pGT,    g_GT);
    cudaGetSymbolAddress((void**)&pGB2,   g_GB2);
    cudaGetSymbolAddress((void**)&pGsumT, g_GsumT);
    cudaGetSymbolAddress((void**)&pW2,    g_W2);

    // Prep
    build_gt  <<<(64 * 4096 + 255) / 256, 256>>>(G);
    build_gb2 <<<(64 * 8192 + 255) / 256, 256>>>(G);
    build_gsum<<<(2 * 64 * 128 + 255) / 256, 256>>>(G);
    build_w2  <<<(512 * 1024 + 255) / 256, 256>>>(Wm);

    // Level 1
    diag_kernel<<<BB * LL, 64>>>(word, preterm);

    {
        int rows = BB * LL;   // 2048
        // feat0 = relu(emb[word] @ Wp + bp)
        dim3 gF(SD >> 6, rows >> 6);
        gemm_k<<<gF, 256>>>(emb, Wp, pF, EMB, SD, LL, word,
                            0, 0, 0,
                            (long)NCELL * SD, SD, triOff(1) * SD, bp, 0);
        // u for level-1 cells (active t in [64,128) -> GsumT v=1)
        dim3 gU(128 >> 6, rows >> 6);
        gemm_k<<<gU, 256>>>(pP, pGsumT + 64 * 128, pU, 64, 128, LL, nullptr,
                            NCELL * SS, SS, triOff(1) * SS + 64,
                            (long)NCELL * SS, SS, triOff(1) * SS, nullptr, 0);
        // T transform for level-1 cells
        dim3 gT(1024 >> 6, rows >> 6);
        gemm_k<<<gT, 256>>>(pF, pW2, pT, SD, 1024, LL, nullptr,
                            NCELL * SD, SD, triOff(1) * SD,
                            (long)NCELL * 1024, 1024, triOff(1) * 1024, nullptr, 0);
        // Rb (bf16) for level-1 cells (t in [64,128) -> GT v=1)
        dim3 gR(4096 >> 6, rows >> 6);
        gemm_k<<<gR, 256>>>(pP, pGT + 64 * 4096, pRb, 64, 4096, LL, nullptr,
                            NCELL * SS, SS, triOff(1) * SS + 64,
                            (long)NCELL * 4096, 4096, triOff(1) * 4096, nullptr, 1);
        // R1L (bf16): [2048 x 8192] = p1_active @ GB2
        dim3 gR1L(8192 >> 6, rows >> 6);
        gemm_k<<<gR1L, 256>>>(pP, pGB2, pR1L, 64, 8192, LL, nullptr,
                              NCELL * SS, SS, triOff(1) * SS + 64,
                              (long)LL * 8192, 8192, 0, nullptr, 1);
    }

    // Levels 2..32
    for (int ln = 2; ln <= LL; ++ln) {
        int nn = LL - ln + 1;
        int cells = BB * nn;
        level_kernel<<<cells, 256>>>(ln, nn, bm);
        if (ln < LL) {
            // Rb for this level (active t in [0,64) -> GT v=0)
            dim3 gR(4096 >> 6, cells >> 6);
            gemm_k<<<gR, 256>>>(pP, pGT, pRb, 64, 4096, nn, nullptr,
                                NCELL * SS, SS, triOff(ln) * SS,
                                (long)NCELL * 4096, 4096, triOff(ln) * 4096, nullptr, 1);
            // u for this level (GsumT v=0)
            dim3 gU(128 >> 6, cells >> 6);
            gemm_k<<<gU, 256>>>(pP, pGsumT, pU, 64, 128, nn, nullptr,
                                NCELL * SS, SS, triOff(ln) * SS,
                                (long)NCELL * SS, SS, triOff(ln) * SS, nullptr, 0);
            // T transform for this level
            dim3 gT(1024 >> 6, cells >> 6);
            gemm_k<<<gT, 256>>>(pF, pW2, pT, SD, 1024, nn, nullptr,
                                NCELL * SD, SD, triOff(ln) * SD,
                                (long)NCELL * 1024, 1024, triOff(ln) * 1024, nullptr, 0);
        }
    }

    // Root
    root_kernel<<<BB, 128>>>(starts, out);
}

// round 10
// speedup vs baseline: 3.2102x; 1.2681x over previous
#include <cuda_runtime.h>
#include <cuda_bf16.h>

// Problem constants
#define BB   64
#define LL   32
#define NT   64
#define TT   64
#define SS   128
#define VV   50000
#define EMB  512
#define SD   512
#define EPSF 1e-9f
#define NCELL 528           // L*(L+1)/2 per batch

// ----------------------------------------------------------------------------
// Persistent scratch (device globals)
// ----------------------------------------------------------------------------
__device__ float         g_chart_p[BB * NCELL * SS];    // 17 MB
__device__ float         g_u      [BB * NCELL * SS];    // 17 MB
__device__ float         g_chart_f[BB * NCELL * SD];    // 69 MB
__device__ float         g_T      [BB * NCELL * 1024];  // 138 MB  (Lt | Rt)
__device__ __nv_bfloat16 g_Rb     [BB * NCELL * 4096];  // 277 MB
__device__ __nv_bfloat16 g_R1L    [BB * LL * 8192];     // 33 MB
__device__ float         g_GsumT  [2][64 * 128];        // GsumT[v][t][s]
// Pre-transposed bf16 B matrices for tensor-core GEMMs ([N][K] layout)
__device__ __nv_bfloat16 g_W2hT[1024 * 512];            // hi split of W2^T
__device__ __nv_bfloat16 g_W2lT[1024 * 512];            // lo split
__device__ __nv_bfloat16 g_GTt [2][4096 * 64];          // GTt[v][j=a*64+s][t]
__device__ __nv_bfloat16 g_GB2t[8192 * 64];             // GB2t[j=a*128+t][s]

__host__ __device__ __forceinline__ int triOff(int len) {
    return ((len - 1) * (66 - len)) >> 1;
}
__device__ __forceinline__ int cellIdx(int b, int i, int len) {
    return b * NCELL + triOff(len) + i;
}

// ----------------------------------------------------------------------------
// Prep kernels
// ----------------------------------------------------------------------------
__global__ void build_gsum(const float* __restrict__ G) {
    int idx = blockIdx.x * 256 + threadIdx.x;           // 2*64*128
    if (idx >= 2 * 64 * 128) return;
    int v = idx >> 13, t = (idx >> 7) & 63, s = idx & 127;
    const float* gp = G + s * 128 + v * 64 + t;
    float sum = 0.f;
    #pragma unroll 8
    for (int a = 0; a < 64; ++a) sum += gp[a * 16384];
    g_GsumT[v][t * 128 + s] = sum;
}

__global__ void build_w2t(const float* __restrict__ Wm) {
    int idx = blockIdx.x * 256 + threadIdx.x;           // 1024*512
    if (idx >= 1024 * 512) return;
    int j = idx >> 9, k = idx & 511;
    float w = (j < 512) ? Wm[k * 512 + j] : Wm[(512 + k) * 512 + (j - 512)];
    __nv_bfloat16 h = __float2bfloat16(w);
    g_W2hT[idx] = h;
    g_W2lT[idx] = __float2bfloat16(w - __bfloat162float(h));
}

__global__ void build_gtt(const float* __restrict__ G) {
    int idx = blockIdx.x * 256 + threadIdx.x;           // 2*4096*64
    if (idx >= 2 * 4096 * 64) return;
    int v = idx >> 18, r = idx & (4096 * 64 - 1);
    int j = r >> 6, t = r & 63;
    int a = j >> 6, s = j & 63;
    g_GTt[v][r] = __float2bfloat16(G[a * 16384 + s * 128 + v * 64 + t]);
}

__global__ void build_gb2t(const float* __restrict__ G) {
    int idx = blockIdx.x * 256 + threadIdx.x;           // 8192*64
    if (idx >= 8192 * 64) return;
    int j = idx >> 6, s = idx & 63;
    int a = j >> 7, t = j & 127;
    g_GB2t[idx] = __float2bfloat16(G[a * 16384 + (64 + s) * 128 + t]);
}

// ----------------------------------------------------------------------------
// Level-1 preterminal distribution
// ----------------------------------------------------------------------------
__global__ void diag_kernel(const int* __restrict__ word,
                            const float* __restrict__ preterm) {
    int c = blockIdx.x;                  // b*32+i
    int tid = threadIdx.x;               // 64 threads
    int w = word[c];
    float v = preterm[tid * VV + w];
    float s = v;
    #pragma unroll
    for (int o = 16; o; o >>= 1) s += __shfl_down_sync(0xffffffffu, s, o);
    __shared__ float red[2];
    if ((tid & 31) == 0) red[tid >> 5] = s;
    __syncthreads();
    float tot = red[0] + red[1] + EPSF;
    int b = c >> 5, i = c & 31;
    float* cp = g_chart_p + (long)cellIdx(b, i, 1) * SS;
    cp[tid]      = 0.f;
    cp[64 + tid] = v / tot;
}

// ----------------------------------------------------------------------------
// Scalar tiled GEMM (kept for feat gather-GEMM and small u-GEMM)
// ----------------------------------------------------------------------------
__global__ void __launch_bounds__(256) gemm_k(
    const float* __restrict__ A, const float* __restrict__ Bm,
    void* __restrict__ C, int K, int N, int n,
    const int* __restrict__ gidx,
    int a_bs, int a_is, int a_cst,
    long c_bs, int c_is, int c_cst,
    const float* __restrict__ bias, int obf16)
{
    __shared__ float As[16][64];
    __shared__ float Bs[16][64];
    int tid  = threadIdx.x;
    int row0 = blockIdx.y << 6, col0 = blockIdx.x << 6;

    int lr = tid >> 2, lk4 = (tid & 3) << 2;
    int r = row0 + lr;
    const float* Aptr;
    if (gidx) {
        Aptr = A + (long)gidx[r] * EMB + lk4;
    } else {
        int b = r / n, i = r - b * n;
        Aptr = A + (long)b * a_bs + (long)i * a_is + a_cst + lk4;
    }
    int bk = tid >> 4, bn4 = (tid & 15) << 2;
    const float* Bptr = Bm + (long)bk * N + col0 + bn4;

    int ty = tid >> 4, tx = tid & 15;
    float acc[4][4];
    #pragma unroll
    for (int ii = 0; ii < 4; ++ii)
        #pragma unroll
        for (int jj = 0; jj < 4; ++jj) acc[ii][jj] = 0.f;

    for (int k0 = 0; k0 < K; k0 += 16) {
        float4 av = *(const float4*)(Aptr + k0);
        float4 bv = *(const float4*)(Bptr + (long)k0 * N);
        if (k0) __syncthreads();
        As[lk4 + 0][lr] = av.x; As[lk4 + 1][lr] = av.y;
        As[lk4 + 2][lr] = av.z; As[lk4 + 3][lr] = av.w;
        *(float4*)&Bs[bk][bn4] = bv;
        __syncthreads();
        #pragma unroll
        for (int kk = 0; kk < 16; ++kk) {
            float4 af = *(const float4*)&As[kk][ty << 2];
            float4 bf = *(const float4*)&Bs[kk][tx << 2];
            float ar[4] = {af.x, af.y, af.z, af.w};
            float br[4] = {bf.x, bf.y, bf.z, bf.w};
            #pragma unroll
            for (int ii = 0; ii < 4; ++ii)
                #pragma unroll
                for (int jj = 0; jj < 4; ++jj)
                    acc[ii][jj] += ar[ii] * br[jj];
        }
    }

    int cc = col0 + (tx << 2);
    #pragma unroll
    for (int ii = 0; ii < 4; ++ii) {
        int rr = row0 + (ty << 2) + ii;
        int b = rr / n, i = rr - b * n;
        long base = (long)b * c_bs + (long)i * c_is + c_cst + cc;
        float v0 = acc[ii][0], v1 = acc[ii][1], v2 = acc[ii][2], v3 = acc[ii][3];
        if (bias) {
            v0 = fmaxf(v0 + bias[cc + 0], 0.f);
            v1 = fmaxf(v1 + bias[cc + 1], 0.f);
            v2 = fmaxf(v2 + bias[cc + 2], 0.f);
            v3 = fmaxf(v3 + bias[cc + 3], 0.f);
        }
        if (obf16) {
            __nv_bfloat162 h0 = __floats2bfloat162_rn(v0, v1);
            __nv_bfloat162 h1 = __floats2bfloat162_rn(v2, v3);
            uint2 pk = make_uint2(*(unsigned*)&h0, *(unsigned*)&h1);
            *(uint2*)((__nv_bfloat16*)C + base) = pk;
        } else {
            *(float4*)((float*)C + base) = make_float4(v0, v1, v2, v3);
        }
    }
}

// ----------------------------------------------------------------------------
// Tensor-core GEMM: C[r][j] = sum_k A[r][k] * Bt[j][k]
//   A fp32, converted to bf16 (hi, and lo if SPLIT) on the fly.
//   Bt pre-transposed bf16 [N][K] (hi + lo if SPLIT).
//   SPLIT=1: compute ah*bh + al*bh + ah*bl (bf16x3, ~fp32-ish accuracy).
//   Block tile 64 x 128, BK=32, 8 warps, warp tile m32 x n32.
// ----------------------------------------------------------------------------
__device__ __forceinline__ void mma_bf16(float* d,
        unsigned a0, unsigned a1, unsigned a2, unsigned a3,
        unsigned b0, unsigned b1) {
    asm volatile(
        "mma.sync.aligned.m16n8k16.row.col.f32.bf16.bf16.f32 "
        "{%0,%1,%2,%3}, {%4,%5,%6,%7}, {%8,%9}, {%0,%1,%2,%3};"
        : "+f"(d[0]), "+f"(d[1]), "+f"(d[2]), "+f"(d[3])
        : "r"(a0), "r"(a1), "r"(a2), "r"(a3), "r"(b0), "r"(b1));
}

#define TPAD 40   // smem row stride in bf16 elements (80B: 16B-aligned, conflict-free)

template<int SPLIT, int OBF16>
__global__ void __launch_bounds__(256) gemm_t(
    const float* __restrict__ A,
    const __nv_bfloat16* __restrict__ Bh,
    const __nv_bfloat16* __restrict__ Bl,
    void* __restrict__ C, int K, int N, int n,
    int a_bs, int a_is, int a_cst,
    long c_bs, int c_is, int c_cst)
{
    __shared__ __nv_bfloat16 Ash[64][TPAD];
    __shared__ __nv_bfloat16 Asl[64][TPAD];
    __shared__ __nv_bfloat16 Bsh[128][TPAD];
    __shared__ __nv_bfloat16 Bsl[128][TPAD];

    int tid  = threadIdx.x;
    int row0 = blockIdx.y << 6, col0 = blockIdx.x << 7;

    // A loader: row = tid>>2 (0..63), 8 floats at k = (tid&3)*8
    int ar = tid >> 2, aq = tid & 3;
    {
        int r = row0 + ar;
        int b = r / n, i = r - b * n;
        A += (long)b * a_bs + (long)i * a_is + a_cst + aq * 8;
    }
    // B loader: n-row = tid>>1 (0..127), 16 bf16 at k = (tid&1)*16
    int brow = tid >> 1, bq = tid & 1;
    const __nv_bfloat16* Bhp = Bh + (long)(col0 + brow) * K + bq * 16;
    const __nv_bfloat16* Blp = SPLIT ? (Bl + (long)(col0 + brow) * K + bq * 16) : Bh;

    // warp mapping: 8 warps = 2 (m) x 4 (n); warp tile m32 x n32
    int w = tid >> 5, lane = tid & 31;
    int m0 = (w >> 2) << 5, n0 = (w & 3) << 5;
    int g = lane >> 2, cq = lane & 3;

    float acc[2][4][4];
    #pragma unroll
    for (int mt = 0; mt < 2; ++mt)
        #pragma unroll
        for (int nt = 0; nt < 4; ++nt)
            #pragma unroll
            for (int e = 0; e < 4; ++e) acc[mt][nt][e] = 0.f;

    for (int k0 = 0; k0 < K; k0 += 32) {
        float4 av0 = *(const float4*)(A + k0);
        float4 av1 = *(const float4*)(A + k0 + 4);
        uint4 bh0 = *(const uint4*)(Bhp + k0);
        uint4 bh1 = *(const uint4*)(Bhp + k0 + 8);
        uint4 bl0, bl1;
        if (SPLIT) {
            bl0 = *(const uint4*)(Blp + k0);
            bl1 = *(const uint4*)(Blp + k0 + 8);
        }
        if (k0) __syncthreads();
        {
            float f[8] = {av0.x, av0.y, av0.z, av0.w, av1.x, av1.y, av1.z, av1.w};
            #pragma unroll
            for (int j = 0; j < 8; j += 2) {
                __nv_bfloat16 h0 = __float2bfloat16(f[j]);
                __nv_bfloat16 h1 = __float2bfloat16(f[j + 1]);
                *(__nv_bfloat162*)&Ash[ar][aq * 8 + j] =
                    __nv_bfloat162(h0, h1);
                if (SPLIT) {
                    __nv_bfloat16 l0 = __float2bfloat16(f[j]     - __bfloat162float(h0));
                    __nv_bfloat16 l1 = __float2bfloat16(f[j + 1] - __bfloat162float(h1));
                    *(__nv_bfloat162*)&Asl[ar][aq * 8 + j] =
                        __nv_bfloat162(l0, l1);
                }
            }
            *(uint4*)&Bsh[brow][bq * 16]     = bh0;
            *(uint4*)&Bsh[brow][bq * 16 + 8] = bh1;
            if (SPLIT) {
                *(uint4*)&Bsl[brow][bq * 16]     = bl0;
                *(uint4*)&Bsl[brow][bq * 16 + 8] = bl1;
            }
        }
        __syncthreads();

        #pragma unroll
        for (int ks = 0; ks < 2; ++ks) {
            int kb = ks << 4;
            unsigned ah[2][4], al[2][4];
            #pragma unroll
            for (int mt = 0; mt < 2; ++mt) {
                int mr = m0 + (mt << 4);
                ah[mt][0] = *(const unsigned*)&Ash[mr + g    ][kb + 2 * cq];
                ah[mt][1] = *(const unsigned*)&Ash[mr + g + 8][kb + 2 * cq];
                ah[mt][2] = *(const unsigned*)&Ash[mr + g    ][kb + 8 + 2 * cq];
                ah[mt][3] = *(const unsigned*)&Ash[mr + g + 8][kb + 8 + 2 * cq];
                if (SPLIT) {
                    al[mt][0] = *(const unsigned*)&Asl[mr + g    ][kb + 2 * cq];
                    al[mt][1] = *(const unsigned*)&Asl[mr + g + 8][kb + 2 * cq];
                    al[mt][2] = *(const unsigned*)&Asl[mr + g    ][kb + 8 + 2 * cq];
                    al[mt][3] = *(const unsigned*)&Asl[mr + g + 8][kb + 8 + 2 * cq];
                }
            }
            #pragma unroll
            for (int nt = 0; nt < 4; ++nt) {
                int nr = n0 + (nt << 3);
                unsigned b0 = *(const unsigned*)&Bsh[nr + g][kb + 2 * cq];
                unsigned b1 = *(const unsigned*)&Bsh[nr + g][kb + 8 + 2 * cq];
                #pragma unroll
                for (int mt = 0; mt < 2; ++mt) {
                    mma_bf16(acc[mt][nt], ah[mt][0], ah[mt][1], ah[mt][2], ah[mt][3], b0, b1);
                    if (SPLIT)
                        mma_bf16(acc[mt][nt], al[mt][0], al[mt][1], al[mt][2], al[mt][3], b0, b1);
                }
                if (SPLIT) {
                    unsigned c0 = *(const unsigned*)&Bsl[nr + g][kb + 2 * cq];
                    unsigned c1 = *(const unsigned*)&Bsl[nr + g][kb + 8 + 2 * cq];
                    #pragma unroll
                    for (int mt = 0; mt < 2; ++mt)
                        mma_bf16(acc[mt][nt], ah[mt][0], ah[mt][1], ah[mt][2], ah[mt][3], c0, c1);
                }
            }
        }
    }

    // Store C
    #pragma unroll
    for (int mt = 0; mt < 2; ++mt) {
        #pragma unroll
        for (int h2 = 0; h2 < 2; ++h2) {
            int rr = row0 + m0 + (mt << 4) + g + (h2 << 3);
            int b = rr / n, i = rr - b * n;
            long base = (long)b * c_bs + (long)i * c_is + c_cst;
            #pragma unroll
            for (int nt = 0; nt < 4; ++nt) {
                int cc = col0 + n0 + (nt << 3) + 2 * cq;
                float v0 = acc[mt][nt][h2 * 2 + 0];
                float v1 = acc[mt][nt][h2 * 2 + 1];
                if (OBF16) {
                    __nv_bfloat162 hv = __floats2bfloat162_rn(v0, v1);
                    *(unsigned*)((__nv_bfloat16*)C + base + cc) = *(unsigned*)&hv;
                } else {
                    *(float2*)((float*)C + base + cc) = make_float2(v0, v1);
                }
            }
        }
    }
}

// ----------------------------------------------------------------------------
// Fused per-level kernel (unchanged from round 9)
// ----------------------------------------------------------------------------
__device__ __forceinline__ float dot16bf(const __nv_bfloat16* __restrict__ r,
                                         const float* s) {
    uint4 v0 = *(const uint4*)r;
    uint4 v1 = *(const uint4*)(r + 8);
    const unsigned* u0 = (const unsigned*)&v0;
    const unsigned* u1 = (const unsigned*)&v1;
    float acc = 0.f;
    #pragma unroll
    for (int w = 0; w < 4; ++w) {
        float2 f0 = __bfloat1622float2(*(const __nv_bfloat162*)&u0[w]);
        float2 f1 = __bfloat1622float2(*(const __nv_bfloat162*)&u1[w]);
        acc += f0.x * s[2 * w]     + f0.y * s[2 * w + 1]
             + f1.x * s[8 + 2 * w] + f1.y * s[8 + 2 * w + 1];
    }
    return acc;
}

__global__ void __launch_bounds__(256) level_kernel(int ln, int n,
                                                    const float* __restrict__ bm) {
    int c = blockIdx.x;
    int b = c / n, i = c - b * n;
    int tid = threadIdx.x;
    int a = tid >> 2, q = tid & 3;
    int t0 = q << 4;
    __shared__ float lp[64], rp[64], us[64], red[2], sc[64], massS[32];
    float acc = 0.f;

    for (int d = 1; d < ln; ++d) {
        int soff = (d == 1) ? 64 : 0;
        int rLen = ln - d;
        int soff_r = (rLen == 1) ? 64 : 0;
        __syncthreads();
        if (tid < 64)
            lp[tid] = g_chart_p[(long)cellIdx(b, i, d) * SS + soff + tid];
        else if (tid < 128)
            us[tid - 64] = g_u[(long)cellIdx(b, i + d, rLen) * SS + soff + (tid - 64)];
        else if (tid < 192)
            rp[tid - 128] = g_chart_p[(long)cellIdx(b, i + d, rLen) * SS + soff_r + (tid - 128)];
        __syncthreads();

        if (tid < 64) {
            float m = lp[tid] * us[tid];
            #pragma unroll
            for (int o = 16; o; o >>= 1) m += __shfl_down_sync(0xffffffffu, m, o);
            if ((tid & 31) == 0) red[tid >> 5] = m;
        }

        if (d == 1) {
            const __nv_bfloat16* Rrow = g_R1L + ((long)(b * LL + i)) * 8192
                                             + a * 128 + soff_r + t0;
            acc += dot16bf(Rrow, rp + t0);
        } else {
            const __nv_bfloat16* Rrow = g_Rb + (long)cellIdx(b, i + d, rLen) * 4096
                                            + a * 64 + t0;
            acc += dot16bf(Rrow, lp + t0);
        }
        __syncthreads();
        if (tid == 0) massS[d - 1] = red[0] + red[1];
    }

    acc += __shfl_down_sync(0xffffffffu, acc, 2);
    acc += __shfl_down_sync(0xffffffffu, acc, 1);
    if (q == 0) sc[a] = acc;
    __syncthreads();
    if (tid < 64) {
        float v = sc[tid];
        #pragma unroll
        for (int o = 16; o; o >>= 1) v += __shfl_down_sync(0xffffffffu, v, o);
        if ((tid & 31) == 0) red[tid >> 5] = v;
    }
    __syncthreads();
    float ptot = red[0] + red[1] + EPSF;
    if (tid < 64)
        g_chart_p[(long)cellIdx(b, i, ln) * SS + tid] = sc[tid] / ptot;

    int D = ln - 1;
    __shared__ float tot_s;
    if (tid == 0) {
        float t = 0.f;
        for (int d = 0; d < D; ++d) t += massS[d];
        tot_s = t + EPSF;
    }
    __syncthreads();
    float bm0 = bm[tid], bm1 = bm[tid + 256];
    float f0 = 0.f, f1 = 0.f;
    for (int d = 1; d <= D; ++d) {
        const float* TL = g_T + (long)cellIdx(b, i, d) * 1024;
        const float* TR = g_T + (long)cellIdx(b, i + d, ln - d) * 1024 + 512;
        float wd = massS[d - 1] / tot_s;
        f0 += wd * fmaxf(TL[tid]       + TR[tid]       + bm0, 0.f);
        f1 += wd * fmaxf(TL[tid + 256] + TR[tid + 256] + bm1, 0.f);
    }
    float* cf = g_chart_f + (long)cellIdx(b, i, ln) * SD;
    cf[tid]       = f0;
    cf[tid + 256] = f1;
}

// ----------------------------------------------------------------------------
// Root
// ----------------------------------------------------------------------------
__global__ void root_kernel(const float* __restrict__ starts, float* __restrict__ out) {
    int b = blockIdx.x, tid = threadIdx.x;  // 128 threads
    const float* p = g_chart_p + (long)cellIdx(b, 0, LL) * SS;
    float v = p[tid] * starts[tid];
    #pragma unroll
    for (int o = 16; o; o >>= 1) v += __shfl_down_sync(0xffffffffu, v, o);
    __shared__ float red[4];
    if ((tid & 31) == 0) red[tid >> 5] = v;
    __syncthreads();
    float score = red[0] + red[1] + red[2] + red[3];
    const float* f = g_chart_f + (long)cellIdx(b, 0, LL) * SD;
    for (int h = tid; h < SD; h += 128) out[b * SD + h] = f[h] * score;
}

// ----------------------------------------------------------------------------
// Host driver
// ----------------------------------------------------------------------------
extern "C" void kernel_launch(void* const* d_in, const int* in_sizes, int n_in,
                              void* d_out, int out_size) {
    const int*   word    = (const int*)  d_in[0];
    const float* emb     = (const float*)d_in[1];
    const float* preterm = (const float*)d_in[2];
    const float* G       = (const float*)d_in[3];
    const float* starts  = (const float*)d_in[4];
    const float* Wp      = (const float*)d_in[5];
    const float* bp      = (const float*)d_in[6];
    const float* Wm      = (const float*)d_in[7];
    const float* bm      = (const float*)d_in[8];
    float* out = (float*)d_out;

    float *pP, *pU, *pF, *pT, *pGsumT;
    __nv_bfloat16 *pRb, *pR1L, *pW2h, *pW2l, *pGTt, *pGB2t;
    cudaGetSymbolAddress((void**)&pP,     g_chart_p);
    cudaGetSymbolAddress((void**)&pU,     g_u);
    cudaGetSymbolAddress((void**)&pF,     g_chart_f);
    cudaGetSymbolAddress((void**)&pT,     g_T);
    cudaGetSymbolAddress((void**)&pRb,    g_Rb);
    cudaGetSymbolAddress((void**)&pR1L,   g_R1L);
    cudaGetSymbolAddress((void**)&pGsumT, g_GsumT);
    cudaGetSymbolAddress((void**)&pW2h,   g_W2hT);
    cudaGetSymbolAddress((void**)&pW2l,   g_W2lT);
    cudaGetSymbolAddress((void**)&pGTt,   g_GTt);
    cudaGetSymbolAddress((void**)&pGB2t,  g_GB2t);

    // Prep
    build_gsum<<<(2 * 64 * 128 + 255) / 256, 256>>>(G);
    build_w2t <<<(1024 * 512 + 255) / 256, 256>>>(Wm);
    build_gtt <<<(2 * 4096 * 64 + 255) / 256, 256>>>(G);
    build_gb2t<<<(8192 * 64 + 255) / 256, 256>>>(G);

    // Level 1
    diag_kernel<<<BB * LL, 64>>>(word, preterm);

    {
        int rows = BB * LL;   // 2048
        // feat0 = relu(emb[word] @ Wp + bp)  (scalar GEMM, gather rows)
        dim3 gF(SD >> 6, rows >> 6);
        gemm_k<<<gF, 256>>>(emb, Wp, pF, EMB, SD, LL, word,
                            0, 0, 0,
                            (long)NCELL * SD, SD, triOff(1) * SD, bp, 0);
        // u level-1 (GsumT v=1)
        dim3 gU(128 >> 6, rows >> 6);
        gemm_k<<<gU, 256>>>(pP, pGsumT + 64 * 128, pU, 64, 128, LL, nullptr,
                            NCELL * SS, SS, triOff(1) * SS + 64,
                            (long)NCELL * SS, SS, triOff(1) * SS, nullptr, 0);
        // T level-1 (tensor, split)
        gemm_t<1, 0><<<dim3(1024 >> 7, rows >> 6), 256>>>(
            pF, pW2h, pW2l, pT, 512, 1024, LL,
            NCELL * SD, SD, triOff(1) * SD,
            (long)NCELL * 1024, 1024, triOff(1) * 1024);
        // Rb level-1 (tensor, plain, bf16 out; GTt v=1)
        gemm_t<0, 1><<<dim3(4096 >> 7, rows >> 6), 256>>>(
            pP, pGTt + 4096 * 64, nullptr, pRb, 64, 4096, LL,
            NCELL * SS, SS, triOff(1) * SS + 64,
            (long)NCELL * 4096, 4096, triOff(1) * 4096);
        // R1L (tensor, plain, bf16 out)
        gemm_t<0, 1><<<dim3(8192 >> 7, rows >> 6), 256>>>(
            pP, pGB2t, nullptr, pR1L, 64, 8192, LL,
            NCELL * SS, SS, triOff(1) * SS + 64,
            (long)LL * 8192, 8192, 0);
    }

    // Levels 2..32
    for (int ln = 2; ln <= LL; ++ln) {
        int nn = LL - ln + 1;
        int cells = BB * nn;
        level_kernel<<<cells, 256>>>(ln, nn, bm);
        if (ln < LL) {
            // Rb (tensor, GTt v=0)
            gemm_t<0, 1><<<dim3(4096 >> 7, cells >> 6), 256>>>(
                pP, pGTt, nullptr, pRb, 64, 4096, nn,
                NCELL * SS, SS, triOff(ln) * SS,
                (long)NCELL * 4096, 4096, triOff(ln) * 4096);
            // u (scalar)
            dim3 gU(128 >> 6, cells >> 6);
            gemm_k<<<gU, 256>>>(pP, pGsumT, pU, 64, 128, nn, nullptr,
                                NCELL * SS, SS, triOff(ln) * SS,
                                (long)NCELL * SS, SS, triOff(ln) * SS, nullptr, 0);
            // T (tensor, split)
            gemm_t<1, 0><<<dim3(1024 >> 7, cells >> 6), 256>>>(
                pF, pW2h, pW2l, pT, 512, 1024, nn,
                NCELL * SD, SD, triOff(ln) * SD,
                (long)NCELL * 1024, 1024, triOff(ln) * 1024);
        }
    }

    // Root
    root_kernel<<<BB, 128>>>(starts, out);
}

// round 11
// speedup vs baseline: 3.6752x; 1.1449x over previous
#include <cuda_runtime.h>
#include <cuda_bf16.h>

// Problem constants
#define BB   64
#define LL   32
#define NT   64
#define TT   64
#define SS   128
#define VV   50000
#define EMB  512
#define SD   512
#define EPSF 1e-9f
#define NCELL 528           // L*(L+1)/2 per batch

// ----------------------------------------------------------------------------
// Persistent scratch (device globals)
// ----------------------------------------------------------------------------
__device__ float         g_chart_p[BB * NCELL * SS];    // 17 MB
__device__ float         g_u      [BB * NCELL * SS];    // 17 MB
__device__ float         g_chart_f[BB * NCELL * SD];    // 69 MB
__device__ float         g_T      [BB * NCELL * 1024];  // 138 MB  (Lt | Rt)
__device__ __nv_bfloat16 g_Rb     [BB * NCELL * 4096];  // 277 MB
__device__ __nv_bfloat16 g_R1L    [BB * LL * 8192];     // 33 MB
__device__ float         g_GsumT  [2][64 * 128];        // GsumT[v][t][s]
// Pre-transposed bf16 B matrices for tensor-core GEMMs ([N][K] layout)
__device__ __nv_bfloat16 g_W2hT[1024 * 512];            // hi split of W2^T
__device__ __nv_bfloat16 g_W2lT[1024 * 512];            // lo split
__device__ __nv_bfloat16 g_GTt [2][4096 * 64];          // GTt[v][j=a*64+s][t]
__device__ __nv_bfloat16 g_GB2t[8192 * 64];             // GB2t[j=a*128+t][s]

__host__ __device__ __forceinline__ int triOff(int len) {
    return ((len - 1) * (66 - len)) >> 1;
}
__device__ __forceinline__ int cellIdx(int b, int i, int len) {
    return b * NCELL + triOff(len) + i;
}

// ----------------------------------------------------------------------------
// Prep kernels
// ----------------------------------------------------------------------------
__global__ void build_gsum(const float* __restrict__ G) {
    int idx = blockIdx.x * 256 + threadIdx.x;           // 2*64*128
    if (idx >= 2 * 64 * 128) return;
    int v = idx >> 13, t = (idx >> 7) & 63, s = idx & 127;
    const float* gp = G + s * 128 + v * 64 + t;
    float sum = 0.f;
    #pragma unroll 8
    for (int a = 0; a < 64; ++a) sum += gp[a * 16384];
    g_GsumT[v][t * 128 + s] = sum;
}

__global__ void build_w2t(const float* __restrict__ Wm) {
    int idx = blockIdx.x * 256 + threadIdx.x;           // 1024*512
    if (idx >= 1024 * 512) return;
    int j = idx >> 9, k = idx & 511;
    float w = (j < 512) ? Wm[k * 512 + j] : Wm[(512 + k) * 512 + (j - 512)];
    __nv_bfloat16 h = __float2bfloat16(w);
    g_W2hT[idx] = h;
    g_W2lT[idx] = __float2bfloat16(w - __bfloat162float(h));
}

__global__ void build_gtt(const float* __restrict__ G) {
    int idx = blockIdx.x * 256 + threadIdx.x;           // 2*4096*64
    if (idx >= 2 * 4096 * 64) return;
    int v = idx >> 18, r = idx & (4096 * 64 - 1);
    int j = r >> 6, t = r & 63;
    int a = j >> 6, s = j & 63;
    g_GTt[v][r] = __float2bfloat16(G[a * 16384 + s * 128 + v * 64 + t]);
}

__global__ void build_gb2t(const float* __restrict__ G) {
    int idx = blockIdx.x * 256 + threadIdx.x;           // 8192*64
    if (idx >= 8192 * 64) return;
    int j = idx >> 6, s = idx & 63;
    int a = j >> 7, t = j & 127;
    g_GB2t[idx] = __float2bfloat16(G[a * 16384 + (64 + s) * 128 + t]);
}

// ----------------------------------------------------------------------------
// Level-1 preterminal distribution
// ----------------------------------------------------------------------------
__global__ void diag_kernel(const int* __restrict__ word,
                            const float* __restrict__ preterm) {
    int c = blockIdx.x;                  // b*32+i
    int tid = threadIdx.x;               // 64 threads
    int w = word[c];
    float v = preterm[tid * VV + w];
    float s = v;
    #pragma unroll
    for (int o = 16; o; o >>= 1) s += __shfl_down_sync(0xffffffffu, s, o);
    __shared__ float red[2];
    if ((tid & 31) == 0) red[tid >> 5] = s;
    __syncthreads();
    float tot = red[0] + red[1] + EPSF;
    int b = c >> 5, i = c & 31;
    float* cp = g_chart_p + (long)cellIdx(b, i, 1) * SS;
    cp[tid]      = 0.f;
    cp[64 + tid] = v / tot;
}

// ----------------------------------------------------------------------------
// Scalar tiled GEMM (feat gather-GEMM and level-1 u-GEMM)
// ----------------------------------------------------------------------------
__global__ void __launch_bounds__(256) gemm_k(
    const float* __restrict__ A, const float* __restrict__ Bm,
    void* __restrict__ C, int K, int N, int n,
    const int* __restrict__ gidx,
    int a_bs, int a_is, int a_cst,
    long c_bs, int c_is, int c_cst,
    const float* __restrict__ bias, int obf16)
{
    __shared__ float As[16][64];
    __shared__ float Bs[16][64];
    int tid  = threadIdx.x;
    int row0 = blockIdx.y << 6, col0 = blockIdx.x << 6;

    int lr = tid >> 2, lk4 = (tid & 3) << 2;
    int r = row0 + lr;
    const float* Aptr;
    if (gidx) {
        Aptr = A + (long)gidx[r] * EMB + lk4;
    } else {
        int b = r / n, i = r - b * n;
        Aptr = A + (long)b * a_bs + (long)i * a_is + a_cst + lk4;
    }
    int bk = tid >> 4, bn4 = (tid & 15) << 2;
    const float* Bptr = Bm + (long)bk * N + col0 + bn4;

    int ty = tid >> 4, tx = tid & 15;
    float acc[4][4];
    #pragma unroll
    for (int ii = 0; ii < 4; ++ii)
        #pragma unroll
        for (int jj = 0; jj < 4; ++jj) acc[ii][jj] = 0.f;

    for (int k0 = 0; k0 < K; k0 += 16) {
        float4 av = *(const float4*)(Aptr + k0);
        float4 bv = *(const float4*)(Bptr + (long)k0 * N);
        if (k0) __syncthreads();
        As[lk4 + 0][lr] = av.x; As[lk4 + 1][lr] = av.y;
        As[lk4 + 2][lr] = av.z; As[lk4 + 3][lr] = av.w;
        *(float4*)&Bs[bk][bn4] = bv;
        __syncthreads();
        #pragma unroll
        for (int kk = 0; kk < 16; ++kk) {
            float4 af = *(const float4*)&As[kk][ty << 2];
            float4 bf = *(const float4*)&Bs[kk][tx << 2];
            float ar[4] = {af.x, af.y, af.z, af.w};
            float br[4] = {bf.x, bf.y, bf.z, bf.w};
            #pragma unroll
            for (int ii = 0; ii < 4; ++ii)
                #pragma unroll
                for (int jj = 0; jj < 4; ++jj)
                    acc[ii][jj] += ar[ii] * br[jj];
        }
    }

    int cc = col0 + (tx << 2);
    #pragma unroll
    for (int ii = 0; ii < 4; ++ii) {
        int rr = row0 + (ty << 2) + ii;
        int b = rr / n, i = rr - b * n;
        long base = (long)b * c_bs + (long)i * c_is + c_cst + cc;
        float v0 = acc[ii][0], v1 = acc[ii][1], v2 = acc[ii][2], v3 = acc[ii][3];
        if (bias) {
            v0 = fmaxf(v0 + bias[cc + 0], 0.f);
            v1 = fmaxf(v1 + bias[cc + 1], 0.f);
            v2 = fmaxf(v2 + bias[cc + 2], 0.f);
            v3 = fmaxf(v3 + bias[cc + 3], 0.f);
        }
        if (obf16) {
            __nv_bfloat162 h0 = __floats2bfloat162_rn(v0, v1);
            __nv_bfloat162 h1 = __floats2bfloat162_rn(v2, v3);
            uint2 pk = make_uint2(*(unsigned*)&h0, *(unsigned*)&h1);
            *(uint2*)((__nv_bfloat16*)C + base) = pk;
        } else {
            *(float4*)((float*)C + base) = make_float4(v0, v1, v2, v3);
        }
    }
}

// ----------------------------------------------------------------------------
// Tensor-core GEMM (round-10 proven): C[r][j] = sum_k A[r][k] * Bt[j][k]
// ----------------------------------------------------------------------------
__device__ __forceinline__ void mma_bf16(float* d,
        unsigned a0, unsigned a1, unsigned a2, unsigned a3,
        unsigned b0, unsigned b1) {
    asm volatile(
        "mma.sync.aligned.m16n8k16.row.col.f32.bf16.bf16.f32 "
        "{%0,%1,%2,%3}, {%4,%5,%6,%7}, {%8,%9}, {%0,%1,%2,%3};"
        : "+f"(d[0]), "+f"(d[1]), "+f"(d[2]), "+f"(d[3])
        : "r"(a0), "r"(a1), "r"(a2), "r"(a3), "r"(b0), "r"(b1));
}

#define TPAD 40

template<int SPLIT, int OBF16>
__global__ void __launch_bounds__(256) gemm_t(
    const float* __restrict__ A,
    const __nv_bfloat16* __restrict__ Bh,
    const __nv_bfloat16* __restrict__ Bl,
    void* __restrict__ C, int K, int N, int n,
    int a_bs, int a_is, int a_cst,
    long c_bs, int c_is, int c_cst)
{
    __shared__ __nv_bfloat16 Ash[64][TPAD];
    __shared__ __nv_bfloat16 Asl[64][TPAD];
    __shared__ __nv_bfloat16 Bsh[128][TPAD];
    __shared__ __nv_bfloat16 Bsl[128][TPAD];

    int tid  = threadIdx.x;
    int row0 = blockIdx.y << 6, col0 = blockIdx.x << 7;

    int ar = tid >> 2, aq = tid & 3;
    {
        int r = row0 + ar;
        int b = r / n, i = r - b * n;
        A += (long)b * a_bs + (long)i * a_is + a_cst + aq * 8;
    }
    int brow = tid >> 1, bq = tid & 1;
    const __nv_bfloat16* Bhp = Bh + (long)(col0 + brow) * K + bq * 16;
    const __nv_bfloat16* Blp = SPLIT ? (Bl + (long)(col0 + brow) * K + bq * 16) : Bh;

    int w = tid >> 5, lane = tid & 31;
    int m0 = (w >> 2) << 5, n0 = (w & 3) << 5;
    int g = lane >> 2, cq = lane & 3;

    float acc[2][4][4];
    #pragma unroll
    for (int mt = 0; mt < 2; ++mt)
        #pragma unroll
        for (int nt = 0; nt < 4; ++nt)
            #pragma unroll
            for (int e = 0; e < 4; ++e) acc[mt][nt][e] = 0.f;

    for (int k0 = 0; k0 < K; k0 += 32) {
        float4 av0 = *(const float4*)(A + k0);
        float4 av1 = *(const float4*)(A + k0 + 4);
        uint4 bh0 = *(const uint4*)(Bhp + k0);
        uint4 bh1 = *(const uint4*)(Bhp + k0 + 8);
        uint4 bl0, bl1;
        if (SPLIT) {
            bl0 = *(const uint4*)(Blp + k0);
            bl1 = *(const uint4*)(Blp + k0 + 8);
        }
        if (k0) __syncthreads();
        {
            float f[8] = {av0.x, av0.y, av0.z, av0.w, av1.x, av1.y, av1.z, av1.w};
            #pragma unroll
            for (int j = 0; j < 8; j += 2) {
                __nv_bfloat16 h0 = __float2bfloat16(f[j]);
                __nv_bfloat16 h1 = __float2bfloat16(f[j + 1]);
                *(__nv_bfloat162*)&Ash[ar][aq * 8 + j] = __nv_bfloat162(h0, h1);
                if (SPLIT) {
                    __nv_bfloat16 l0 = __float2bfloat16(f[j]     - __bfloat162float(h0));
                    __nv_bfloat16 l1 = __float2bfloat16(f[j + 1] - __bfloat162float(h1));
                    *(__nv_bfloat162*)&Asl[ar][aq * 8 + j] = __nv_bfloat162(l0, l1);
                }
            }
            *(uint4*)&Bsh[brow][bq * 16]     = bh0;
            *(uint4*)&Bsh[brow][bq * 16 + 8] = bh1;
            if (SPLIT) {
                *(uint4*)&Bsl[brow][bq * 16]     = bl0;
                *(uint4*)&Bsl[brow][bq * 16 + 8] = bl1;
            }
        }
        __syncthreads();

        #pragma unroll
        for (int ks = 0; ks < 2; ++ks) {
            int kb = ks << 4;
            unsigned ah[2][4], al[2][4];
            #pragma unroll
            for (int mt = 0; mt < 2; ++mt) {
                int mr = m0 + (mt << 4);
                ah[mt][0] = *(const unsigned*)&Ash[mr + g    ][kb + 2 * cq];
                ah[mt][1] = *(const unsigned*)&Ash[mr + g + 8][kb + 2 * cq];
                ah[mt][2] = *(const unsigned*)&Ash[mr + g    ][kb + 8 + 2 * cq];
                ah[mt][3] = *(const unsigned*)&Ash[mr + g + 8][kb + 8 + 2 * cq];
                if (SPLIT) {
                    al[mt][0] = *(const unsigned*)&Asl[mr + g    ][kb + 2 * cq];
                    al[mt][1] = *(const unsigned*)&Asl[mr + g + 8][kb + 2 * cq];
                    al[mt][2] = *(const unsigned*)&Asl[mr + g    ][kb + 8 + 2 * cq];
                    al[mt][3] = *(const unsigned*)&Asl[mr + g + 8][kb + 8 + 2 * cq];
                }
            }
            #pragma unroll
            for (int nt = 0; nt < 4; ++nt) {
                int nr = n0 + (nt << 3);
                unsigned b0 = *(const unsigned*)&Bsh[nr + g][kb + 2 * cq];
                unsigned b1 = *(const unsigned*)&Bsh[nr + g][kb + 8 + 2 * cq];
                #pragma unroll
                for (int mt = 0; mt < 2; ++mt) {
                    mma_bf16(acc[mt][nt], ah[mt][0], ah[mt][1], ah[mt][2], ah[mt][3], b0, b1);
                    if (SPLIT)
                        mma_bf16(acc[mt][nt], al[mt][0], al[mt][1], al[mt][2], al[mt][3], b0, b1);
                }
                if (SPLIT) {
                    unsigned c0 = *(const unsigned*)&Bsl[nr + g][kb + 2 * cq];
                    unsigned c1 = *(const unsigned*)&Bsl[nr + g][kb + 8 + 2 * cq];
                    #pragma unroll
                    for (int mt = 0; mt < 2; ++mt)
                        mma_bf16(acc[mt][nt], ah[mt][0], ah[mt][1], ah[mt][2], ah[mt][3], c0, c1);
                }
            }
        }
    }

    #pragma unroll
    for (int mt = 0; mt < 2; ++mt) {
        #pragma unroll
        for (int h2 = 0; h2 < 2; ++h2) {
            int rr = row0 + m0 + (mt << 4) + g + (h2 << 3);
            int b = rr / n, i = rr - b * n;
            long base = (long)b * c_bs + (long)i * c_is + c_cst;
            #pragma unroll
            for (int nt = 0; nt < 4; ++nt) {
                int cc = col0 + n0 + (nt << 3) + 2 * cq;
                float v0 = acc[mt][nt][h2 * 2 + 0];
                float v1 = acc[mt][nt][h2 * 2 + 1];
                if (OBF16) {
                    __nv_bfloat162 hv = __floats2bfloat162_rn(v0, v1);
                    *(unsigned*)((__nv_bfloat16*)C + base + cc) = *(unsigned*)&hv;
                } else {
                    *(float2*)((float*)C + base + cc) = make_float2(v0, v1);
                }
            }
        }
    }
}

// ----------------------------------------------------------------------------
// Fused per-level kernel, software-pipelined; also computes u in the epilogue.
// ----------------------------------------------------------------------------
__device__ __forceinline__ float dot16bf(const __nv_bfloat16* __restrict__ r,
                                         const float* s) {
    uint4 v0 = *(const uint4*)r;
    uint4 v1 = *(const uint4*)(r + 8);
    const unsigned* u0 = (const unsigned*)&v0;
    const unsigned* u1 = (const unsigned*)&v1;
    float acc = 0.f;
    #pragma unroll
    for (int w = 0; w < 4; ++w) {
        float2 f0 = __bfloat1622float2(*(const __nv_bfloat162*)&u0[w]);
        float2 f1 = __bfloat1622float2(*(const __nv_bfloat162*)&u1[w]);
        acc += f0.x * s[2 * w]     + f0.y * s[2 * w + 1]
             + f1.x * s[8 + 2 * w] + f1.y * s[8 + 2 * w + 1];
    }
    return acc;
}

__global__ void __launch_bounds__(256) level_kernel(int ln, int n,
                                                    const float* __restrict__ bm,
                                                    int computeU) {
    int c = blockIdx.x;
    int b = c / n, i = c - b * n;
    int tid = threadIdx.x;
    int a = tid >> 2, q = tid & 3;
    int t0 = q << 4;
    __shared__ float lp[64], rp[64], us[64], red[2], sc[64];
    __shared__ float mp0[32], mp1[32], massS[32], upart[256];
    __shared__ float tot_s;
    float acc = 0.f;

    // stage split d=1
    float stage = 0.f;
    {
        int rLen = ln - 1;
        int soff_r = (rLen == 1) ? 64 : 0;
        if (tid < 64)
            stage = g_chart_p[(long)cellIdx(b, i, 1) * SS + 64 + tid];
        else if (tid < 128)
            stage = g_u[(long)cellIdx(b, i + 1, rLen) * SS + 64 + (tid - 64)];
        else if (tid < 192)
            stage = g_chart_p[(long)cellIdx(b, i + 1, rLen) * SS + soff_r + (tid - 128)];
    }

    for (int d = 1; d < ln; ++d) {
        int rLen = ln - d;
        __syncthreads();                       // previous compute finished with smem
        if (tid < 64)       lp[tid] = stage;
        else if (tid < 128) us[tid - 64] = stage;
        else if (tid < 192) rp[tid - 128] = stage;
        __syncthreads();

        // prefetch split d+1 (overlaps with compute below)
        if (d + 1 < ln) {
            int dn = d + 1, rLn = ln - dn;
            int soff_rn = (rLn == 1) ? 64 : 0;
            if (tid < 64)
                stage = g_chart_p[(long)cellIdx(b, i, dn) * SS + tid];            // dn>=2 -> soff 0
            else if (tid < 128)
                stage = g_u[(long)cellIdx(b, i + dn, rLn) * SS + (tid - 64)];
            else if (tid < 192)
                stage = g_chart_p[(long)cellIdx(b, i + dn, rLn) * SS + soff_rn + (tid - 128)];
        }

        // mass_d partials (warps 0,1)
        if (tid < 64) {
            float m = lp[tid] * us[tid];
            #pragma unroll
            for (int o = 16; o; o >>= 1) m += __shfl_down_sync(0xffffffffu, m, o);
            if (tid == 0)       mp0[d - 1] = m;
            else if (tid == 32) mp1[d - 1] = m;
        }

        // score dot
        if (d == 1) {
            int soff_r = (rLen == 1) ? 64 : 0;
            const __nv_bfloat16* Rrow = g_R1L + ((long)(b * LL + i)) * 8192
                                             + a * 128 + soff_r + t0;
            acc += dot16bf(Rrow, rp + t0);
        } else {
            const __nv_bfloat16* Rrow = g_Rb + (long)cellIdx(b, i + d, rLen) * 4096
                                            + a * 64 + t0;
            acc += dot16bf(Rrow, lp + t0);
        }
    }

    // reduce scores over q
    acc += __shfl_down_sync(0xffffffffu, acc, 2);
    acc += __shfl_down_sync(0xffffffffu, acc, 1);
    int D = ln - 1;
    __syncthreads();                           // S1: loop done, mp* visible
    if (q == 0) sc[a] = acc;
    if (tid >= 128 && tid - 128 < D) {
        int d2 = tid - 128;
        massS[d2] = mp0[d2] + mp1[d2];
    }
    __syncthreads();                           // S2: sc + massS visible
    if (tid < 64) {
        float v = sc[tid];
        #pragma unroll
        for (int o = 16; o; o >>= 1) v += __shfl_down_sync(0xffffffffu, v, o);
        if ((tid & 31) == 0) red[tid >> 5] = v;
    } else if (tid == 64) {
        float t = 0.f;
        for (int d2 = 0; d2 < D; ++d2) t += massS[d2];
        tot_s = t + EPSF;
    }
    __syncthreads();                           // S3: red + tot_s visible
    float ptot = red[0] + red[1] + EPSF;
    if (tid < 64) {
        float pv = sc[tid] / ptot;
        g_chart_p[(long)cellIdx(b, i, ln) * SS + tid] = pv;
        lp[tid] = pv;                          // keep normalized p for u epilogue
    }

    // ---- combine phase ----
    float bm0 = bm[tid], bm1 = bm[tid + 256];
    float f0 = 0.f, f1 = 0.f;
    #pragma unroll 2
    for (int d = 1; d <= D; ++d) {
        const float* TL = g_T + (long)cellIdx(b, i, d) * 1024;
        const float* TR = g_T + (long)cellIdx(b, i + d, ln - d) * 1024 + 512;
        float wd = massS[d - 1] / tot_s;
        f0 += wd * fmaxf(TL[tid]       + TR[tid]       + bm0, 0.f);
        f1 += wd * fmaxf(TL[tid + 256] + TR[tid + 256] + bm1, 0.f);
    }
    float* cf = g_chart_f + (long)cellIdx(b, i, ln) * SD;
    cf[tid]       = f0;
    cf[tid + 256] = f1;

    // ---- u epilogue: u[j] = sum_t GsumT[0][t*128+j] * p[t], t in [0,64) ----
    if (computeU) {
        __syncthreads();                       // lp (normalized p) visible
        int j = tid & 127, h = tid >> 7;       // h: t-range half
        const float* gs = g_GsumT[0] + j;
        float partial = 0.f;
        #pragma unroll 8
        for (int t = 0; t < 32; ++t)
            partial += gs[(h * 32 + t) * 128] * lp[h * 32 + t];
        upart[tid] = partial;
        __syncthreads();
        if (tid < 128)
            g_u[(long)cellIdx(b, i, ln) * SS + tid] = upart[tid] + upart[tid + 128];
    }
}

// ----------------------------------------------------------------------------
// Root
// ----------------------------------------------------------------------------
__global__ void root_kernel(const float* __restrict__ starts, float* __restrict__ out) {
    int b = blockIdx.x, tid = threadIdx.x;  // 128 threads
    const float* p = g_chart_p + (long)cellIdx(b, 0, LL) * SS;
    float v = p[tid] * starts[tid];
    #pragma unroll
    for (int o = 16; o; o >>= 1) v += __shfl_down_sync(0xffffffffu, v, o);
    __shared__ float red[4];
    if ((tid & 31) == 0) red[tid >> 5] = v;
    __syncthreads();
    float score = red[0] + red[1] + red[2] + red[3];
    const float* f = g_chart_f + (long)cellIdx(b, 0, LL) * SD;
    for (int h = tid; h < SD; h += 128) out[b * SD + h] = f[h] * score;
}

// ----------------------------------------------------------------------------
// Host driver
// ----------------------------------------------------------------------------
extern "C" void kernel_launch(void* const* d_in, const int* in_sizes, int n_in,
                              void* d_out, int out_size) {
    const int*   word    = (const int*)  d_in[0];
    const float* emb     = (const float*)d_in[1];
    const float* preterm = (const float*)d_in[2];
    const float* G       = (const float*)d_in[3];
    const float* starts  = (const float*)d_in[4];
    const float* Wp      = (const float*)d_in[5];
    const float* bp      = (const float*)d_in[6];
    const float* Wm      = (const float*)d_in[7];
    const float* bm      = (const float*)d_in[8];
    float* out = (float*)d_out;

    float *pP, *pU, *pF, *pT, *pGsumT;
    __nv_bfloat16 *pRb, *pR1L, *pW2h, *pW2l, *pGTt, *pGB2t;
    cudaGetSymbolAddress((void**)&pP,     g_chart_p);
    cudaGetSymbolAddress((void**)&pU,     g_u);
    cudaGetSymbolAddress((void**)&pF,     g_chart_f);
    cudaGetSymbolAddress((void**)&pT,     g_T);
    cudaGetSymbolAddress((void**)&pRb,    g_Rb);
    cudaGetSymbolAddress((void**)&pR1L,   g_R1L);
    cudaGetSymbolAddress((void**)&pGsumT, g_GsumT);
    cudaGetSymbolAddress((void**)&pW2h,   g_W2hT);
    cudaGetSymbolAddress((void**)&pW2l,   g_W2lT);
    cudaGetSymbolAddress((void**)&pGTt,   g_GTt);
    cudaGetSymbolAddress((void**)&pGB2t,  g_GB2t);

    // Prep
    build_gsum<<<(2 * 64 * 128 + 255) / 256, 256>>>(G);
    build_w2t <<<(1024 * 512 + 255) / 256, 256>>>(Wm);
    build_gtt <<<(2 * 4096 * 64 + 255) / 256, 256>>>(G);
    build_gb2t<<<(8192 * 64 + 255) / 256, 256>>>(G);

    // Level 1
    diag_kernel<<<BB * LL, 64>>>(word, preterm);

    {
        int rows = BB * LL;   // 2048
        // feat0 = relu(emb[word] @ Wp + bp)  (scalar GEMM, gather rows)
        dim3 gF(SD >> 6, rows >> 6);
        gemm_k<<<gF, 256>>>(emb, Wp, pF, EMB, SD, LL, word,
                            0, 0, 0,
                            (long)NCELL * SD, SD, triOff(1) * SD, bp, 0);
        // u level-1 (GsumT v=1)
        dim3 gU(128 >> 6, rows >> 6);
        gemm_k<<<gU, 256>>>(pP, pGsumT + 64 * 128, pU, 64, 128, LL, nullptr,
                            NCELL * SS, SS, triOff(1) * SS + 64,
                            (long)NCELL * SS, SS, triOff(1) * SS, nullptr, 0);
        // T level-1 (tensor, split)
        gemm_t<1, 0><<<dim3(1024 >> 7, rows >> 6), 256>>>(
            pF, pW2h, pW2l, pT, 512, 1024, LL,
            NCELL * SD, SD, triOff(1) * SD,
            (long)NCELL * 1024, 1024, triOff(1) * 1024);
        // Rb level-1 (tensor, plain, bf16 out; GTt v=1)
        gemm_t<0, 1><<<dim3(4096 >> 7, rows >> 6), 256>>>(
            pP, pGTt + 4096 * 64, nullptr, pRb, 64, 4096, LL,
            NCELL * SS, SS, triOff(1) * SS + 64,
            (long)NCELL * 4096, 4096, triOff(1) * 4096);
        // R1L (tensor, plain, bf16 out)
        gemm_t<0, 1><<<dim3(8192 >> 7, rows >> 6), 256>>>(
            pP, pGB2t, nullptr, pR1L, 64, 8192, LL,
            NCELL * SS, SS, triOff(1) * SS + 64,
            (long)LL * 8192, 8192, 0);
    }

    // Levels 2..32
    for (int ln = 2; ln <= LL; ++ln) {
        int nn = LL - ln + 1;
        int cells = BB * nn;
        level_kernel<<<cells, 256>>>(ln, nn, bm, (ln < LL) ? 1 : 0);
        if (ln < LL) {
            // Rb (tensor, GTt v=0)
            gemm_t<0, 1><<<dim3(4096 >> 7, cells >> 6), 256>>>(
                pP, pGTt, nullptr, pRb, 64, 4096, nn,
                NCELL * SS, SS, triOff(ln) * SS,
                (long)NCELL * 4096, 4096, triOff(ln) * 4096);
            // T (tensor, split)
            gemm_t<1, 0><<<dim3(1024 >> 7, cells >> 6), 256>>>(
                pF, pW2h, pW2l, pT, 512, 1024, nn,
                NCELL * SD, SD, triOff(ln) * SD,
                (long)NCELL * 1024, 1024, triOff(ln) * 1024);
        }
    }

    // Root
    root_kernel<<<BB, 128>>>(starts, out);
}

// round 12
// speedup vs baseline: 4.4706x; 1.2164x over previous
#include <cuda_runtime.h>
#include <cuda_bf16.h>

// Problem constants
#define BB   64
#define LL   32
#define NT   64
#define TT   64
#define SS   128
#define VV   50000
#define EMB  512
#define SD   512
#define EPSF 1e-9f
#define NCELL 528           // L*(L+1)/2 per batch

// ----------------------------------------------------------------------------
// Persistent scratch (device globals)
// ----------------------------------------------------------------------------
__device__ float         g_chart_p[BB * NCELL * SS];    // 17 MB
__device__ float         g_u      [BB * NCELL * SS];    // 17 MB
__device__ float         g_chart_f[BB * NCELL * SD];    // 69 MB
__device__ float         g_T      [BB * NCELL * 1024];  // 138 MB  (Lt | Rt)
__device__ __nv_bfloat16 g_Rb     [BB * NCELL * 4096];  // 277 MB
__device__ __nv_bfloat16 g_R1L    [BB * LL * 8192];     // 33 MB
__device__ float         g_GsumT  [2][64 * 128];        // GsumT[v][t][s]
// Pre-transposed bf16 B matrices for tensor-core GEMMs ([N][K] layout)
__device__ __nv_bfloat16 g_W2hT[1024 * 512];            // hi split of W2^T
__device__ __nv_bfloat16 g_W2lT[1024 * 512];            // lo split
__device__ __nv_bfloat16 g_GTt [2][4096 * 64];          // GTt[v][j=a*64+s][t]
__device__ __nv_bfloat16 g_GB2t[8192 * 64];             // GB2t[j=a*128+t][s]

__host__ __device__ __forceinline__ int triOff(int len) {
    return ((len - 1) * (66 - len)) >> 1;
}
__device__ __forceinline__ int cellIdx(int b, int i, int len) {
    return b * NCELL + triOff(len) + i;
}

// ----------------------------------------------------------------------------
// Prep kernels
// ----------------------------------------------------------------------------
__global__ void build_gsum(const float* __restrict__ G) {
    int idx = blockIdx.x * 256 + threadIdx.x;           // 2*64*128
    if (idx >= 2 * 64 * 128) return;
    int v = idx >> 13, t = (idx >> 7) & 63, s = idx & 127;
    const float* gp = G + s * 128 + v * 64 + t;
    float sum = 0.f;
    #pragma unroll 8
    for (int a = 0; a < 64; ++a) sum += gp[a * 16384];
    g_GsumT[v][t * 128 + s] = sum;
}

__global__ void build_w2t(const float* __restrict__ Wm) {
    int idx = blockIdx.x * 256 + threadIdx.x;           // 1024*512
    if (idx >= 1024 * 512) return;
    int j = idx >> 9, k = idx & 511;
    float w = (j < 512) ? Wm[k * 512 + j] : Wm[(512 + k) * 512 + (j - 512)];
    __nv_bfloat16 h = __float2bfloat16(w);
    g_W2hT[idx] = h;
    g_W2lT[idx] = __float2bfloat16(w - __bfloat162float(h));
}

__global__ void build_gtt(const float* __restrict__ G) {
    int idx = blockIdx.x * 256 + threadIdx.x;           // 2*4096*64
    if (idx >= 2 * 4096 * 64) return;
    int v = idx >> 18, r = idx & (4096 * 64 - 1);
    int j = r >> 6, t = r & 63;
    int a = j >> 6, s = j & 63;
    g_GTt[v][r] = __float2bfloat16(G[a * 16384 + s * 128 + v * 64 + t]);
}

__global__ void build_gb2t(const float* __restrict__ G) {
    int idx = blockIdx.x * 256 + threadIdx.x;           // 8192*64
    if (idx >= 8192 * 64) return;
    int j = idx >> 6, s = idx & 63;
    int a = j >> 7, t = j & 127;
    g_GB2t[idx] = __float2bfloat16(G[a * 16384 + (64 + s) * 128 + t]);
}

// ----------------------------------------------------------------------------
// Level-1 preterminal distribution
// ----------------------------------------------------------------------------
__global__ void diag_kernel(const int* __restrict__ word,
                            const float* __restrict__ preterm) {
    int c = blockIdx.x;                  // b*32+i
    int tid = threadIdx.x;               // 64 threads
    int w = word[c];
    float v = preterm[tid * VV + w];
    float s = v;
    #pragma unroll
    for (int o = 16; o; o >>= 1) s += __shfl_down_sync(0xffffffffu, s, o);
    __shared__ float red[2];
    if ((tid & 31) == 0) red[tid >> 5] = s;
    __syncthreads();
    float tot = red[0] + red[1] + EPSF;
    int b = c >> 5, i = c & 31;
    float* cp = g_chart_p + (long)cellIdx(b, i, 1) * SS;
    cp[tid]      = 0.f;
    cp[64 + tid] = v / tot;
}

// ----------------------------------------------------------------------------
// Scalar tiled GEMM (feat gather-GEMM and level-1 u-GEMM)
// ----------------------------------------------------------------------------
__global__ void __launch_bounds__(256) gemm_k(
    const float* __restrict__ A, const float* __restrict__ Bm,
    void* __restrict__ C, int K, int N, int n,
    const int* __restrict__ gidx,
    int a_bs, int a_is, int a_cst,
    long c_bs, int c_is, int c_cst,
    const float* __restrict__ bias, int obf16)
{
    __shared__ float As[16][64];
    __shared__ float Bs[16][64];
    int tid  = threadIdx.x;
    int row0 = blockIdx.y << 6, col0 = blockIdx.x << 6;

    int lr = tid >> 2, lk4 = (tid & 3) << 2;
    int r = row0 + lr;
    const float* Aptr;
    if (gidx) {
        Aptr = A + (long)gidx[r] * EMB + lk4;
    } else {
        int b = r / n, i = r - b * n;
        Aptr = A + (long)b * a_bs + (long)i * a_is + a_cst + lk4;
    }
    int bk = tid >> 4, bn4 = (tid & 15) << 2;
    const float* Bptr = Bm + (long)bk * N + col0 + bn4;

    int ty = tid >> 4, tx = tid & 15;
    float acc[4][4];
    #pragma unroll
    for (int ii = 0; ii < 4; ++ii)
        #pragma unroll
        for (int jj = 0; jj < 4; ++jj) acc[ii][jj] = 0.f;

    for (int k0 = 0; k0 < K; k0 += 16) {
        float4 av = *(const float4*)(Aptr + k0);
        float4 bv = *(const float4*)(Bptr + (long)k0 * N);
        if (k0) __syncthreads();
        As[lk4 + 0][lr] = av.x; As[lk4 + 1][lr] = av.y;
        As[lk4 + 2][lr] = av.z; As[lk4 + 3][lr] = av.w;
        *(float4*)&Bs[bk][bn4] = bv;
        __syncthreads();
        #pragma unroll
        for (int kk = 0; kk < 16; ++kk) {
            float4 af = *(const float4*)&As[kk][ty << 2];
            float4 bf = *(const float4*)&Bs[kk][tx << 2];
            float ar[4] = {af.x, af.y, af.z, af.w};
            float br[4] = {bf.x, bf.y, bf.z, bf.w};
            #pragma unroll
            for (int ii = 0; ii < 4; ++ii)
                #pragma unroll
                for (int jj = 0; jj < 4; ++jj)
                    acc[ii][jj] += ar[ii] * br[jj];
        }
    }

    int cc = col0 + (tx << 2);
    #pragma unroll
    for (int ii = 0; ii < 4; ++ii) {
        int rr = row0 + (ty << 2) + ii;
        int b = rr / n, i = rr - b * n;
        long base = (long)b * c_bs + (long)i * c_is + c_cst + cc;
        float v0 = acc[ii][0], v1 = acc[ii][1], v2 = acc[ii][2], v3 = acc[ii][3];
        if (bias) {
            v0 = fmaxf(v0 + bias[cc + 0], 0.f);
            v1 = fmaxf(v1 + bias[cc + 1], 0.f);
            v2 = fmaxf(v2 + bias[cc + 2], 0.f);
            v3 = fmaxf(v3 + bias[cc + 3], 0.f);
        }
        if (obf16) {
            __nv_bfloat162 h0 = __floats2bfloat162_rn(v0, v1);
            __nv_bfloat162 h1 = __floats2bfloat162_rn(v2, v3);
            uint2 pk = make_uint2(*(unsigned*)&h0, *(unsigned*)&h1);
            *(uint2*)((__nv_bfloat16*)C + base) = pk;
        } else {
            *(float4*)((float*)C + base) = make_float4(v0, v1, v2, v3);
        }
    }
}

// ----------------------------------------------------------------------------
// Tensor-core GEMM body (device function; smem carved from dynamic buffer)
// C[r][j] = sum_k A[r][k] * Bt[j][k].  Block tile 64 x 128, BK=32.
// ----------------------------------------------------------------------------
__device__ __forceinline__ void mma_bf16(float* d,
        unsigned a0, unsigned a1, unsigned a2, unsigned a3,
        unsigned b0, unsigned b1) {
    asm volatile(
        "mma.sync.aligned.m16n8k16.row.col.f32.bf16.bf16.f32 "
        "{%0,%1,%2,%3}, {%4,%5,%6,%7}, {%8,%9}, {%0,%1,%2,%3};"
        : "+f"(d[0]), "+f"(d[1]), "+f"(d[2]), "+f"(d[3])
        : "r"(a0), "r"(a1), "r"(a2), "r"(a3), "r"(b0), "r"(b1));
}

#define TPAD 40   // smem row stride in bf16 (80B = 5x16B: uint4-aligned rows)
#define GT_SMEM (2 * (64 * TPAD + 64 * TPAD + 128 * TPAD + 128 * TPAD))  // 30720 B

template<int SPLIT, int OBF16>
__device__ __forceinline__ void gemm_t_body(
    char* smbase, int bx, int by,
    const float* __restrict__ A,
    const __nv_bfloat16* __restrict__ Bh,
    const __nv_bfloat16* __restrict__ Bl,
    void* __restrict__ C, int K, int N, int n,
    int a_bs, int a_is, int a_cst,
    long c_bs, int c_is, int c_cst)
{
    typedef __nv_bfloat16 bf;
    bf (*Ash)[TPAD] = (bf(*)[TPAD])(smbase);
    bf (*Asl)[TPAD] = (bf(*)[TPAD])(smbase + 5120);
    bf (*Bsh)[TPAD] = (bf(*)[TPAD])(smbase + 10240);
    bf (*Bsl)[TPAD] = (bf(*)[TPAD])(smbase + 20480);

    int tid  = threadIdx.x;
    int row0 = by << 6, col0 = bx << 7;

    int ar = tid >> 2, aq = tid & 3;
    {
        int r = row0 + ar;
        int b = r / n, i = r - b * n;
        A += (long)b * a_bs + (long)i * a_is + a_cst + aq * 8;
    }
    int brow = tid >> 1, bq = tid & 1;
    const bf* Bhp = Bh + (long)(col0 + brow) * K + bq * 16;
    const bf* Blp = SPLIT ? (Bl + (long)(col0 + brow) * K + bq * 16) : Bh;

    int w = tid >> 5, lane = tid & 31;
    int m0 = (w >> 2) << 5, n0 = (w & 3) << 5;
    int g = lane >> 2, cq = lane & 3;

    float acc[2][4][4];
    #pragma unroll
    for (int mt = 0; mt < 2; ++mt)
        #pragma unroll
        for (int nt = 0; nt < 4; ++nt)
            #pragma unroll
            for (int e = 0; e < 4; ++e) acc[mt][nt][e] = 0.f;

    for (int k0 = 0; k0 < K; k0 += 32) {
        float4 av0 = *(const float4*)(A + k0);
        float4 av1 = *(const float4*)(A + k0 + 4);
        uint4 bh0 = *(const uint4*)(Bhp + k0);
        uint4 bh1 = *(const uint4*)(Bhp + k0 + 8);
        uint4 bl0, bl1;
        if (SPLIT) {
            bl0 = *(const uint4*)(Blp + k0);
            bl1 = *(const uint4*)(Blp + k0 + 8);
        }
        if (k0) __syncthreads();
        {
            float f[8] = {av0.x, av0.y, av0.z, av0.w, av1.x, av1.y, av1.z, av1.w};
            #pragma unroll
            for (int j = 0; j < 8; j += 2) {
                __nv_bfloat16 h0 = __float2bfloat16(f[j]);
                __nv_bfloat16 h1 = __float2bfloat16(f[j + 1]);
                *(__nv_bfloat162*)&Ash[ar][aq * 8 + j] = __nv_bfloat162(h0, h1);
                if (SPLIT) {
                    __nv_bfloat16 l0 = __float2bfloat16(f[j]     - __bfloat162float(h0));
                    __nv_bfloat16 l1 = __float2bfloat16(f[j + 1] - __bfloat162float(h1));
                    *(__nv_bfloat162*)&Asl[ar][aq * 8 + j] = __nv_bfloat162(l0, l1);
                }
            }
            *(uint4*)&Bsh[brow][bq * 16]     = bh0;
            *(uint4*)&Bsh[brow][bq * 16 + 8] = bh1;
            if (SPLIT) {
                *(uint4*)&Bsl[brow][bq * 16]     = bl0;
                *(uint4*)&Bsl[brow][bq * 16 + 8] = bl1;
            }
        }
        __syncthreads();

        #pragma unroll
        for (int ks = 0; ks < 2; ++ks) {
            int kb = ks << 4;
            unsigned ah[2][4], al[2][4];
            #pragma unroll
            for (int mt = 0; mt < 2; ++mt) {
                int mr = m0 + (mt << 4);
                ah[mt][0] = *(const unsigned*)&Ash[mr + g    ][kb + 2 * cq];
                ah[mt][1] = *(const unsigned*)&Ash[mr + g + 8][kb + 2 * cq];
                ah[mt][2] = *(const unsigned*)&Ash[mr + g    ][kb + 8 + 2 * cq];
                ah[mt][3] = *(const unsigned*)&Ash[mr + g + 8][kb + 8 + 2 * cq];
                if (SPLIT) {
                    al[mt][0] = *(const unsigned*)&Asl[mr + g    ][kb + 2 * cq];
                    al[mt][1] = *(const unsigned*)&Asl[mr + g + 8][kb + 2 * cq];
                    al[mt][2] = *(const unsigned*)&Asl[mr + g    ][kb + 8 + 2 * cq];
                    al[mt][3] = *(const unsigned*)&Asl[mr + g + 8][kb + 8 + 2 * cq];
                }
            }
            #pragma unroll
            for (int nt = 0; nt < 4; ++nt) {
                int nr = n0 + (nt << 3);
                unsigned b0 = *(const unsigned*)&Bsh[nr + g][kb + 2 * cq];
                unsigned b1 = *(const unsigned*)&Bsh[nr + g][kb + 8 + 2 * cq];
                #pragma unroll
                for (int mt = 0; mt < 2; ++mt) {
                    mma_bf16(acc[mt][nt], ah[mt][0], ah[mt][1], ah[mt][2], ah[mt][3], b0, b1);
                    if (SPLIT)
                        mma_bf16(acc[mt][nt], al[mt][0], al[mt][1], al[mt][2], al[mt][3], b0, b1);
                }
                if (SPLIT) {
                    unsigned c0 = *(const unsigned*)&Bsl[nr + g][kb + 2 * cq];
                    unsigned c1 = *(const unsigned*)&Bsl[nr + g][kb + 8 + 2 * cq];
                    #pragma unroll
                    for (int mt = 0; mt < 2; ++mt)
                        mma_bf16(acc[mt][nt], ah[mt][0], ah[mt][1], ah[mt][2], ah[mt][3], c0, c1);
                }
            }
        }
    }

    #pragma unroll
    for (int mt = 0; mt < 2; ++mt) {
        #pragma unroll
        for (int h2 = 0; h2 < 2; ++h2) {
            int rr = row0 + m0 + (mt << 4) + g + (h2 << 3);
            int b = rr / n, i = rr - b * n;
            long base = (long)b * c_bs + (long)i * c_is + c_cst;
            #pragma unroll
            for (int nt = 0; nt < 4; ++nt) {
                int cc = col0 + n0 + (nt << 3) + 2 * cq;
                float v0 = acc[mt][nt][h2 * 2 + 0];
                float v1 = acc[mt][nt][h2 * 2 + 1];
                if (OBF16) {
                    __nv_bfloat162 hv = __floats2bfloat162_rn(v0, v1);
                    *(unsigned*)((__nv_bfloat16*)C + base + cc) = *(unsigned*)&hv;
                } else {
                    *(float2*)((float*)C + base + cc) = make_float2(v0, v1);
                }
            }
        }
    }
}

// ----------------------------------------------------------------------------
// Fused per-level GEMM dispatcher: T (split), Rb, optionally R1L in one grid.
//   blocks [0, yb*8)            : T     (64x128 tiles over [rows x 1024])
//   blocks [yb*8, yb*8+yb*32)   : Rb    (64x128 tiles over [rows x 4096])
//   blocks [.., +yb*64)         : R1L   (level 1 only, [rows x 8192])
// ----------------------------------------------------------------------------
__global__ void __launch_bounds__(256) level_gemms(
    const float* __restrict__ P, const float* __restrict__ F,
    const __nv_bfloat16* __restrict__ GTtv,
    const __nv_bfloat16* __restrict__ W2h, const __nv_bfloat16* __restrict__ W2l,
    const __nv_bfloat16* __restrict__ GB2t,
    __nv_bfloat16* __restrict__ Rb, float* __restrict__ T,
    __nv_bfloat16* __restrict__ R1L,
    int n, int yb,
    int aP_cst, int cR_cst, int aF_cst, int cT_cst)
{
    extern __shared__ char sm[];
    int nT = yb * 8, nR = yb * 32;
    int bid = blockIdx.x;
    if (bid < nT) {
        gemm_t_body<1, 0>(sm, bid & 7, bid >> 3, F, W2h, W2l, T, 512, 1024, n,
                          NCELL * SD, SD, aF_cst, (long)NCELL * 1024, 1024, cT_cst);
    } else if (bid < nT + nR) {
        int r = bid - nT;
        gemm_t_body<0, 1>(sm, r & 31, r >> 5, P, GTtv, nullptr, Rb, 64, 4096, n,
                          NCELL * SS, SS, aP_cst, (long)NCELL * 4096, 4096, cR_cst);
    } else {
        int r = bid - nT - nR;
        gemm_t_body<0, 1>(sm, r & 63, r >> 6, P, GB2t, nullptr, R1L, 64, 8192, n,
                          NCELL * SS, SS, aP_cst, (long)LL * 8192, 8192, 0);
    }
}

// ----------------------------------------------------------------------------
// Fused per-level kernel: scores + masses -> normalize -> combine -> u.
// Pipelined: smem operands AND the 8KB R row are prefetched one split ahead.
// ----------------------------------------------------------------------------
__device__ __forceinline__ float dot16v(uint4 v0, uint4 v1, const float* s) {
    const unsigned* u0 = (const unsigned*)&v0;
    const unsigned* u1 = (const unsigned*)&v1;
    float acc = 0.f;
    #pragma unroll
    for (int w = 0; w < 4; ++w) {
        float2 f0 = __bfloat1622float2(*(const __nv_bfloat162*)&u0[w]);
        float2 f1 = __bfloat1622float2(*(const __nv_bfloat162*)&u1[w]);
        acc += f0.x * s[2 * w]     + f0.y * s[2 * w + 1]
             + f1.x * s[8 + 2 * w] + f1.y * s[8 + 2 * w + 1];
    }
    return acc;
}

__global__ void __launch_bounds__(256) level_kernel(int ln, int n,
                                                    const float* __restrict__ bm,
                                                    int computeU) {
    int c = blockIdx.x;
    int b = c / n, i = c - b * n;
    int tid = threadIdx.x;
    int a = tid >> 2, q = tid & 3;
    int t0 = q << 4;
    __shared__ float lp[64], rp[64], us[64], red[2], sc[64];
    __shared__ float mp0[32], mp1[32], massS[32], upart[256];
    __shared__ float tot_s;
    float acc = 0.f;

    // stage split d=1: smem operands + R row
    float stage = 0.f;
    {
        int rLen = ln - 1;
        int soff_r = (rLen == 1) ? 64 : 0;
        if (tid < 64)
            stage = g_chart_p[(long)cellIdx(b, i, 1) * SS + 64 + tid];
        else if (tid < 128)
            stage = g_u[(long)cellIdx(b, i + 1, rLen) * SS + 64 + (tid - 64)];
        else if (tid < 192)
            stage = g_chart_p[(long)cellIdx(b, i + 1, rLen) * SS + soff_r + (tid - 128)];
    }
    uint4 rv0, rv1;
    {
        int rLen = ln - 1;
        int soff_r = (rLen == 1) ? 64 : 0;
        const __nv_bfloat16* rP = g_R1L + ((long)(b * LL + i)) * 8192
                                        + a * 128 + soff_r + t0;
        rv0 = *(const uint4*)rP;
        rv1 = *(const uint4*)(rP + 8);
    }

    for (int d = 1; d < ln; ++d) {
        __syncthreads();                       // previous compute done with smem
        if (tid < 64)       lp[tid] = stage;
        else if (tid < 128) us[tid - 64] = stage;
        else if (tid < 192) rp[tid - 128] = stage;
        __syncthreads();

        // prefetch split d+1 (smem operands + R row) — overlaps compute below
        uint4 nv0, nv1;
        if (d + 1 < ln) {
            int dn = d + 1, rLn = ln - dn;
            int soff_rn = (rLn == 1) ? 64 : 0;
            if (tid < 64)
                stage = g_chart_p[(long)cellIdx(b, i, dn) * SS + tid];
            else if (tid < 128)
                stage = g_u[(long)cellIdx(b, i + dn, rLn) * SS + (tid - 64)];
            else if (tid < 192)
                stage = g_chart_p[(long)cellIdx(b, i + dn, rLn) * SS + soff_rn + (tid - 128)];
            const __nv_bfloat16* nP = g_Rb + (long)cellIdx(b, i + dn, rLn) * 4096
                                           + a * 64 + t0;   // dn >= 2 always Rb
            nv0 = *(const uint4*)nP;
            nv1 = *(const uint4*)(nP + 8);
        }

        // mass_d partials (warps 0,1)
        if (tid < 64) {
            float m = lp[tid] * us[tid];
            #pragma unroll
            for (int o = 16; o; o >>= 1) m += __shfl_down_sync(0xffffffffu, m, o);
            if (tid == 0)       mp0[d - 1] = m;
            else if (tid == 32) mp1[d - 1] = m;
        }

        // score dot (R row already in registers)
        acc += dot16v(rv0, rv1, (d == 1 ? rp : lp) + t0);
        rv0 = nv0; rv1 = nv1;
    }

    // reduce scores over q
    acc += __shfl_down_sync(0xffffffffu, acc, 2);
    acc += __shfl_down_sync(0xffffffffu, acc, 1);
    int D = ln - 1;
    __syncthreads();                           // loop done, mp* visible
    if (q == 0) sc[a] = acc;
    if (tid >= 128 && tid - 128 < D) {
        int d2 = tid - 128;
        massS[d2] = mp0[d2] + mp1[d2];
    }
    __syncthreads();                           // sc + massS visible
    if (tid < 64) {
        float v = sc[tid];
        #pragma unroll
        for (int o = 16; o; o >>= 1) v += __shfl_down_sync(0xffffffffu, v, o);
        if ((tid & 31) == 0) red[tid >> 5] = v;
    } else if (tid == 64) {
        float t = 0.f;
        for (int d2 = 0; d2 < D; ++d2) t += massS[d2];
        tot_s = t + EPSF;
    }
    __syncthreads();                           // red + tot_s visible
    float ptot = red[0] + red[1] + EPSF;
    if (tid < 64) {
        float pv = sc[tid] / ptot;
        g_chart_p[(long)cellIdx(b, i, ln) * SS + tid] = pv;
        lp[tid] = pv;                          // normalized p for u epilogue
    }

    // ---- combine phase (float2 per thread: elements 2*tid, 2*tid+1) ----
    float2 bmv = *(const float2*)(bm + 2 * tid);
    float2 f = make_float2(0.f, 0.f);
    #pragma unroll 2
    for (int d = 1; d <= D; ++d) {
        const float* TLp = g_T + (long)cellIdx(b, i, d) * 1024;
        const float* TRp = g_T + (long)cellIdx(b, i + d, ln - d) * 1024 + 512;
        float2 tl = *(const float2*)(TLp + 2 * tid);
        float2 tr = *(const float2*)(TRp + 2 * tid);
        float wd = massS[d - 1] / tot_s;
        f.x += wd * fmaxf(tl.x + tr.x + bmv.x, 0.f);
        f.y += wd * fmaxf(tl.y + tr.y + bmv.y, 0.f);
    }
    *(float2*)(g_chart_f + (long)cellIdx(b, i, ln) * SD + 2 * tid) = f;

    // ---- u epilogue: u[j] = sum_t GsumT[0][t*128+j] * p[t], t in [0,64) ----
    if (computeU) {
        __syncthreads();                       // lp (normalized p) visible
        int j = tid & 127, h = tid >> 7;
        const float* gs = g_GsumT[0] + j;
        float partial = 0.f;
        #pragma unroll 8
        for (int t = 0; t < 32; ++t)
            partial += gs[(h * 32 + t) * 128] * lp[h * 32 + t];
        upart[tid] = partial;
        __syncthreads();
        if (tid < 128)
            g_u[(long)cellIdx(b, i, ln) * SS + tid] = upart[tid] + upart[tid + 128];
    }
}

// ----------------------------------------------------------------------------
// Root
// ----------------------------------------------------------------------------
__global__ void root_kernel(const float* __restrict__ starts, float* __restrict__ out) {
    int b = blockIdx.x, tid = threadIdx.x;  // 128 threads
    const float* p = g_chart_p + (long)cellIdx(b, 0, LL) * SS;
    float v = p[tid] * starts[tid];
    #pragma unroll
    for (int o = 16; o; o >>= 1) v += __shfl_down_sync(0xffffffffu, v, o);
    __shared__ float red[4];
    if ((tid & 31) == 0) red[tid >> 5] = v;
    __syncthreads();
    float score = red[0] + red[1] + red[2] + red[3];
    const float* f = g_chart_f + (long)cellIdx(b, 0, LL) * SD;
    for (int h = tid; h < SD; h += 128) out[b * SD + h] = f[h] * score;
}

// ----------------------------------------------------------------------------
// Host driver
// ----------------------------------------------------------------------------
extern "C" void kernel_launch(void* const* d_in, const int* in_sizes, int n_in,
                              void* d_out, int out_size) {
    const int*   word    = (const int*)  d_in[0];
    const float* emb     = (const float*)d_in[1];
    const float* preterm = (const float*)d_in[2];
    const float* G       = (const float*)d_in[3];
    const float* starts  = (const float*)d_in[4];
    const float* Wp      = (const float*)d_in[5];
    const float* bp      = (const float*)d_in[6];
    const float* Wm      = (const float*)d_in[7];
    const float* bm      = (const float*)d_in[8];
    float* out = (float*)d_out;

    float *pP, *pU, *pF, *pT, *pGsumT;
    __nv_bfloat16 *pRb, *pR1L, *pW2h, *pW2l, *pGTt, *pGB2t;
    cudaGetSymbolAddress((void**)&pP,     g_chart_p);
    cudaGetSymbolAddress((void**)&pU,     g_u);
    cudaGetSymbolAddress((void**)&pF,     g_chart_f);
    cudaGetSymbolAddress((void**)&pT,     g_T);
    cudaGetSymbolAddress((void**)&pRb,    g_Rb);
    cudaGetSymbolAddress((void**)&pR1L,   g_R1L);
    cudaGetSymbolAddress((void**)&pGsumT, g_GsumT);
    cudaGetSymbolAddress((void**)&pW2h,   g_W2hT);
    cudaGetSymbolAddress((void**)&pW2l,   g_W2lT);
    cudaGetSymbolAddress((void**)&pGTt,   g_GTt);
    cudaGetSymbolAddress((void**)&pGB2t,  g_GB2t);

    // Prep
    build_gsum<<<(2 * 64 * 128 + 255) / 256, 256>>>(G);
    build_w2t <<<(1024 * 512 + 255) / 256, 256>>>(Wm);
    build_gtt <<<(2 * 4096 * 64 + 255) / 256, 256>>>(G);
    build_gb2t<<<(8192 * 64 + 255) / 256, 256>>>(G);

    // Level 1
    diag_kernel<<<BB * LL, 64>>>(word, preterm);

    {
        int rows = BB * LL;   // 2048
        // feat0 = relu(emb[word] @ Wp + bp)  (scalar GEMM, gather rows)
        dim3 gF(SD >> 6, rows >> 6);
        gemm_k<<<gF, 256>>>(emb, Wp, pF, EMB, SD, LL, word,
                            0, 0, 0,
                            (long)NCELL * SD, SD, triOff(1) * SD, bp, 0);
        // u level-1 (GsumT v=1)
        dim3 gU(128 >> 6, rows >> 6);
        gemm_k<<<gU, 256>>>(pP, pGsumT + 64 * 128, pU, 64, 128, LL, nullptr,
                            NCELL * SS, SS, triOff(1) * SS + 64,
                            (long)NCELL * SS, SS, triOff(1) * SS, nullptr, 0);
        // Fused T + Rb + R1L for level-1 (one launch)
        int yb = rows >> 6;                       // 32
        int blocks = yb * 8 + yb * 32 + yb * 64;  // 3328
        level_gemms<<<blocks, 256, GT_SMEM>>>(
            pP, pF, pGTt + 4096 * 64, pW2h, pW2l, pGB2t,
            pRb, pT, pR1L, LL, yb,
            triOff(1) * SS + 64, triOff(1) * 4096,
            triOff(1) * SD, triOff(1) * 1024);
    }

    // Levels 2..32
    for (int ln = 2; ln <= LL; ++ln) {
        int nn = LL - ln + 1;
        int cells = BB * nn;
        level_kernel<<<cells, 256>>>(ln, nn, bm, (ln < LL) ? 1 : 0);
        if (ln < LL) {
            int yb = nn;                          // cells/64
            int blocks = yb * 8 + yb * 32;        // T + Rb fused
            level_gemms<<<blocks, 256, GT_SMEM>>>(
                pP, pF, pGTt, pW2h, pW2l, pGB2t,
                pRb, pT, pR1L, nn, yb,
                triOff(ln) * SS, triOff(ln) * 4096,
                triOff(ln) * SD, triOff(ln) * 1024);
        }
    }

    // Root
    root_kernel<<<BB, 128>>>(starts, out);
}

// round 13
// speedup vs baseline: 4.7314x; 1.0584x over previous
#include <cuda_runtime.h>
#include <cuda_bf16.h>

// Problem constants
#define BB   64
#define LL   32
#define NT   64
#define TT   64
#define SS   128
#define VV   50000
#define EMB  512
#define SD   512
#define EPSF 1e-9f
#define NCELL 528           // L*(L+1)/2 per batch

// ----------------------------------------------------------------------------
// Persistent scratch (device globals)
// ----------------------------------------------------------------------------
__device__ float         g_chart_p[BB * NCELL * SS];    // 17 MB
__device__ float         g_u      [BB * NCELL * SS];    // 17 MB
__device__ float         g_chart_f[BB * NCELL * SD];    // 69 MB
__device__ float         g_T      [BB * NCELL * 1024];  // 138 MB  (Lt | Rt)
__device__ __nv_bfloat16 g_Rb     [BB * NCELL * 4096];  // 277 MB
__device__ __nv_bfloat16 g_R1L    [BB * LL * 8192];     // 33 MB
__device__ float         g_GsumT  [2][64 * 128];        // GsumT[v][t][s]
// Pre-transposed bf16 B matrices for tensor-core GEMMs ([N][K] layout)
__device__ __nv_bfloat16 g_W2hT[1024 * 512];            // hi split of W2^T
__device__ __nv_bfloat16 g_W2lT[1024 * 512];            // lo split
__device__ __nv_bfloat16 g_GTt [2][4096 * 64];          // GTt[v][j=a*64+s][t]
__device__ __nv_bfloat16 g_GB2t[8192 * 64];             // GB2t[j=a*128+t][s]

__host__ __device__ __forceinline__ int triOff(int len) {
    return ((len - 1) * (66 - len)) >> 1;
}
__device__ __forceinline__ int cellIdx(int b, int i, int len) {
    return b * NCELL + triOff(len) + i;
}

// ----------------------------------------------------------------------------
// Single fused prep kernel: gsum | w2t | gtt | gb2t by block range
//   [0,64)        gsum   (2*64*128 elems)
//   [64,2112)     w2t    (1024*512)
//   [2112,4160)   gtt    (2*4096*64)
//   [4160,6208)   gb2t   (8192*64)
// ----------------------------------------------------------------------------
__global__ void prep_all(const float* __restrict__ G, const float* __restrict__ Wm) {
    int bid = blockIdx.x;
    int tid = threadIdx.x;
    if (bid < 64) {
        int idx = bid * 256 + tid;                      // 2*64*128
        int v = idx >> 13, t = (idx >> 7) & 63, s = idx & 127;
        const float* gp = G + s * 128 + v * 64 + t;
        float sum = 0.f;
        #pragma unroll 8
        for (int a = 0; a < 64; ++a) sum += gp[a * 16384];
        g_GsumT[v][t * 128 + s] = sum;
    } else if (bid < 2112) {
        int idx = (bid - 64) * 256 + tid;               // 1024*512
        int j = idx >> 9, k = idx & 511;
        float w = (j < 512) ? Wm[k * 512 + j] : Wm[(512 + k) * 512 + (j - 512)];
        __nv_bfloat16 h = __float2bfloat16(w);
        g_W2hT[idx] = h;
        g_W2lT[idx] = __float2bfloat16(w - __bfloat162float(h));
    } else if (bid < 4160) {
        int idx = (bid - 2112) * 256 + tid;             // 2*4096*64
        int v = idx >> 18, r = idx & (4096 * 64 - 1);
        int j = r >> 6, t = r & 63;
        int a = j >> 6, s = j & 63;
        g_GTt[v][r] = __float2bfloat16(G[a * 16384 + s * 128 + v * 64 + t]);
    } else {
        int idx = (bid - 4160) * 256 + tid;             // 8192*64
        int j = idx >> 6, s = idx & 63;
        int a = j >> 7, t = j & 127;
        g_GB2t[idx] = __float2bfloat16(G[a * 16384 + (64 + s) * 128 + t]);
    }
}

// ----------------------------------------------------------------------------
// Level-1: preterminal distribution + u1 epilogue (fused)
// ----------------------------------------------------------------------------
__global__ void diag_kernel(const int* __restrict__ word,
                            const float* __restrict__ preterm) {
    int c = blockIdx.x;                  // b*32+i
    int tid = threadIdx.x;               // 128 threads
    int w = word[c];
    __shared__ float ps[64], red2[2];
    float v = 0.f;
    if (tid < 64) {
        v = preterm[tid * VV + w];
        float s = v;
        #pragma unroll
        for (int o = 16; o; o >>= 1) s += __shfl_down_sync(0xffffffffu, s, o);
        if ((tid & 31) == 0) red2[tid >> 5] = s;
    }
    __syncthreads();
    float tot = red2[0] + red2[1] + EPSF;
    int b = c >> 5, i = c & 31;
    long cb = (long)cellIdx(b, i, 1) * SS;
    if (tid < 64) {
        float pv = v / tot;
        g_chart_p[cb + tid]      = 0.f;
        g_chart_p[cb + 64 + tid] = pv;
        ps[tid] = pv;
    }
    __syncthreads();
    // u1[j] = sum_t GsumT[1][t*128+j] * p1[t]
    const float* gs = g_GsumT[1] + tid;
    float u = 0.f;
    #pragma unroll 8
    for (int t = 0; t < 64; ++t) u += gs[t * 128] * ps[t];
    g_u[cb + tid] = u;
}

// ----------------------------------------------------------------------------
// Scalar tiled GEMM (feat gather-GEMM only)
// ----------------------------------------------------------------------------
__global__ void __launch_bounds__(256) gemm_k(
    const float* __restrict__ A, const float* __restrict__ Bm,
    void* __restrict__ C, int K, int N, int n,
    const int* __restrict__ gidx,
    int a_bs, int a_is, int a_cst,
    long c_bs, int c_is, int c_cst,
    const float* __restrict__ bias, int obf16)
{
    __shared__ float As[16][64];
    __shared__ float Bs[16][64];
    int tid  = threadIdx.x;
    int row0 = blockIdx.y << 6, col0 = blockIdx.x << 6;

    int lr = tid >> 2, lk4 = (tid & 3) << 2;
    int r = row0 + lr;
    const float* Aptr;
    if (gidx) {
        Aptr = A + (long)gidx[r] * EMB + lk4;
    } else {
        int b = r / n, i = r - b * n;
        Aptr = A + (long)b * a_bs + (long)i * a_is + a_cst + lk4;
    }
    int bk = tid >> 4, bn4 = (tid & 15) << 2;
    const float* Bptr = Bm + (long)bk * N + col0 + bn4;

    int ty = tid >> 4, tx = tid & 15;
    float acc[4][4];
    #pragma unroll
    for (int ii = 0; ii < 4; ++ii)
        #pragma unroll
        for (int jj = 0; jj < 4; ++jj) acc[ii][jj] = 0.f;

    for (int k0 = 0; k0 < K; k0 += 16) {
        float4 av = *(const float4*)(Aptr + k0);
        float4 bv = *(const float4*)(Bptr + (long)k0 * N);
        if (k0) __syncthreads();
        As[lk4 + 0][lr] = av.x; As[lk4 + 1][lr] = av.y;
        As[lk4 + 2][lr] = av.z; As[lk4 + 3][lr] = av.w;
        *(float4*)&Bs[bk][bn4] = bv;
        __syncthreads();
        #pragma unroll
        for (int kk = 0; kk < 16; ++kk) {
            float4 af = *(const float4*)&As[kk][ty << 2];
            float4 bf = *(const float4*)&Bs[kk][tx << 2];
            float ar[4] = {af.x, af.y, af.z, af.w};
            float br[4] = {bf.x, bf.y, bf.z, bf.w};
            #pragma unroll
            for (int ii = 0; ii < 4; ++ii)
                #pragma unroll
                for (int jj = 0; jj < 4; ++jj)
                    acc[ii][jj] += ar[ii] * br[jj];
        }
    }

    int cc = col0 + (tx << 2);
    #pragma unroll
    for (int ii = 0; ii < 4; ++ii) {
        int rr = row0 + (ty << 2) + ii;
        int b = rr / n, i = rr - b * n;
        long base = (long)b * c_bs + (long)i * c_is + c_cst + cc;
        float v0 = acc[ii][0], v1 = acc[ii][1], v2 = acc[ii][2], v3 = acc[ii][3];
        if (bias) {
            v0 = fmaxf(v0 + bias[cc + 0], 0.f);
            v1 = fmaxf(v1 + bias[cc + 1], 0.f);
            v2 = fmaxf(v2 + bias[cc + 2], 0.f);
            v3 = fmaxf(v3 + bias[cc + 3], 0.f);
        }
        if (obf16) {
            __nv_bfloat162 h0 = __floats2bfloat162_rn(v0, v1);
            __nv_bfloat162 h1 = __floats2bfloat162_rn(v2, v3);
            uint2 pk = make_uint2(*(unsigned*)&h0, *(unsigned*)&h1);
            *(uint2*)((__nv_bfloat16*)C + base) = pk;
        } else {
            *(float4*)((float*)C + base) = make_float4(v0, v1, v2, v3);
        }
    }
}

// ----------------------------------------------------------------------------
// Tensor-core GEMM body (round-12 proven)
// ----------------------------------------------------------------------------
__device__ __forceinline__ void mma_bf16(float* d,
        unsigned a0, unsigned a1, unsigned a2, unsigned a3,
        unsigned b0, unsigned b1) {
    asm volatile(
        "mma.sync.aligned.m16n8k16.row.col.f32.bf16.bf16.f32 "
        "{%0,%1,%2,%3}, {%4,%5,%6,%7}, {%8,%9}, {%0,%1,%2,%3};"
        : "+f"(d[0]), "+f"(d[1]), "+f"(d[2]), "+f"(d[3])
        : "r"(a0), "r"(a1), "r"(a2), "r"(a3), "r"(b0), "r"(b1));
}

#define TPAD 40
#define GT_SMEM (2 * (64 * TPAD + 64 * TPAD + 128 * TPAD + 128 * TPAD))  // 30720 B

template<int SPLIT, int OBF16>
__device__ __forceinline__ void gemm_t_body(
    char* smbase, int bx, int by,
    const float* __restrict__ A,
    const __nv_bfloat16* __restrict__ Bh,
    const __nv_bfloat16* __restrict__ Bl,
    void* __restrict__ C, int K, int N, int n,
    int a_bs, int a_is, int a_cst,
    long c_bs, int c_is, int c_cst)
{
    typedef __nv_bfloat16 bf;
    bf (*Ash)[TPAD] = (bf(*)[TPAD])(smbase);
    bf (*Asl)[TPAD] = (bf(*)[TPAD])(smbase + 5120);
    bf (*Bsh)[TPAD] = (bf(*)[TPAD])(smbase + 10240);
    bf (*Bsl)[TPAD] = (bf(*)[TPAD])(smbase + 20480);

    int tid  = threadIdx.x;
    int row0 = by << 6, col0 = bx << 7;

    int ar = tid >> 2, aq = tid & 3;
    {
        int r = row0 + ar;
        int b = r / n, i = r - b * n;
        A += (long)b * a_bs + (long)i * a_is + a_cst + aq * 8;
    }
    int brow = tid >> 1, bq = tid & 1;
    const bf* Bhp = Bh + (long)(col0 + brow) * K + bq * 16;
    const bf* Blp = SPLIT ? (Bl + (long)(col0 + brow) * K + bq * 16) : Bh;

    int w = tid >> 5, lane = tid & 31;
    int m0 = (w >> 2) << 5, n0 = (w & 3) << 5;
    int g = lane >> 2, cq = lane & 3;

    float acc[2][4][4];
    #pragma unroll
    for (int mt = 0; mt < 2; ++mt)
        #pragma unroll
        for (int nt = 0; nt < 4; ++nt)
            #pragma unroll
            for (int e = 0; e < 4; ++e) acc[mt][nt][e] = 0.f;

    for (int k0 = 0; k0 < K; k0 += 32) {
        float4 av0 = *(const float4*)(A + k0);
        float4 av1 = *(const float4*)(A + k0 + 4);
        uint4 bh0 = *(const uint4*)(Bhp + k0);
        uint4 bh1 = *(const uint4*)(Bhp + k0 + 8);
        uint4 bl0, bl1;
        if (SPLIT) {
            bl0 = *(const uint4*)(Blp + k0);
            bl1 = *(const uint4*)(Blp + k0 + 8);
        }
        if (k0) __syncthreads();
        {
            float f[8] = {av0.x, av0.y, av0.z, av0.w, av1.x, av1.y, av1.z, av1.w};
            #pragma unroll
            for (int j = 0; j < 8; j += 2) {
                __nv_bfloat16 h0 = __float2bfloat16(f[j]);
                __nv_bfloat16 h1 = __float2bfloat16(f[j + 1]);
                *(__nv_bfloat162*)&Ash[ar][aq * 8 + j] = __nv_bfloat162(h0, h1);
                if (SPLIT) {
                    __nv_bfloat16 l0 = __float2bfloat16(f[j]     - __bfloat162float(h0));
                    __nv_bfloat16 l1 = __float2bfloat16(f[j + 1] - __bfloat162float(h1));
                    *(__nv_bfloat162*)&Asl[ar][aq * 8 + j] = __nv_bfloat162(l0, l1);
                }
            }
            *(uint4*)&Bsh[brow][bq * 16]     = bh0;
            *(uint4*)&Bsh[brow][bq * 16 + 8] = bh1;
            if (SPLIT) {
                *(uint4*)&Bsl[brow][bq * 16]     = bl0;
                *(uint4*)&Bsl[brow][bq * 16 + 8] = bl1;
            }
        }
        __syncthreads();

        #pragma unroll
        for (int ks = 0; ks < 2; ++ks) {
            int kb = ks << 4;
            unsigned ah[2][4], al[2][4];
            #pragma unroll
            for (int mt = 0; mt < 2; ++mt) {
                int mr = m0 + (mt << 4);
                ah[mt][0] = *(const unsigned*)&Ash[mr + g    ][kb + 2 * cq];
                ah[mt][1] = *(const unsigned*)&Ash[mr + g + 8][kb + 2 * cq];
                ah[mt][2] = *(const unsigned*)&Ash[mr + g    ][kb + 8 + 2 * cq];
                ah[mt][3] = *(const unsigned*)&Ash[mr + g + 8][kb + 8 + 2 * cq];
                if (SPLIT) {
                    al[mt][0] = *(const unsigned*)&Asl[mr + g    ][kb + 2 * cq];
                    al[mt][1] = *(const unsigned*)&Asl[mr + g + 8][kb + 2 * cq];
                    al[mt][2] = *(const unsigned*)&Asl[mr + g    ][kb + 8 + 2 * cq];
                    al[mt][3] = *(const unsigned*)&Asl[mr + g + 8][kb + 8 + 2 * cq];
                }
            }
            #pragma unroll
            for (int nt = 0; nt < 4; ++nt) {
                int nr = n0 + (nt << 3);
                unsigned b0 = *(const unsigned*)&Bsh[nr + g][kb + 2 * cq];
                unsigned b1 = *(const unsigned*)&Bsh[nr + g][kb + 8 + 2 * cq];
                #pragma unroll
                for (int mt = 0; mt < 2; ++mt) {
                    mma_bf16(acc[mt][nt], ah[mt][0], ah[mt][1], ah[mt][2], ah[mt][3], b0, b1);
                    if (SPLIT)
                        mma_bf16(acc[mt][nt], al[mt][0], al[mt][1], al[mt][2], al[mt][3], b0, b1);
                }
                if (SPLIT) {
                    unsigned c0 = *(const unsigned*)&Bsl[nr + g][kb + 2 * cq];
                    unsigned c1 = *(const unsigned*)&Bsl[nr + g][kb + 8 + 2 * cq];
                    #pragma unroll
                    for (int mt = 0; mt < 2; ++mt)
                        mma_bf16(acc[mt][nt], ah[mt][0], ah[mt][1], ah[mt][2], ah[mt][3], c0, c1);
                }
            }
        }
    }

    #pragma unroll
    for (int mt = 0; mt < 2; ++mt) {
        #pragma unroll
        for (int h2 = 0; h2 < 2; ++h2) {
            int rr = row0 + m0 + (mt << 4) + g + (h2 << 3);
            int b = rr / n, i = rr - b * n;
            long base = (long)b * c_bs + (long)i * c_is + c_cst;
            #pragma unroll
            for (int nt = 0; nt < 4; ++nt) {
                int cc = col0 + n0 + (nt << 3) + 2 * cq;
                float v0 = acc[mt][nt][h2 * 2 + 0];
                float v1 = acc[mt][nt][h2 * 2 + 1];
                if (OBF16) {
                    __nv_bfloat162 hv = __floats2bfloat162_rn(v0, v1);
                    *(unsigned*)((__nv_bfloat16*)C + base + cc) = *(unsigned*)&hv;
                } else {
                    *(float2*)((float*)C + base + cc) = make_float2(v0, v1);
                }
            }
        }
    }
}

// ----------------------------------------------------------------------------
// Fused per-level GEMM dispatcher (round-12 proven)
// ----------------------------------------------------------------------------
__global__ void __launch_bounds__(256) level_gemms(
    const float* __restrict__ P, const float* __restrict__ F,
    const __nv_bfloat16* __restrict__ GTtv,
    const __nv_bfloat16* __restrict__ W2h, const __nv_bfloat16* __restrict__ W2l,
    const __nv_bfloat16* __restrict__ GB2t,
    __nv_bfloat16* __restrict__ Rb, float* __restrict__ T,
    __nv_bfloat16* __restrict__ R1L,
    int n, int yb,
    int aP_cst, int cR_cst, int aF_cst, int cT_cst)
{
    extern __shared__ char sm[];
    int nT = yb * 8, nR = yb * 32;
    int bid = blockIdx.x;
    if (bid < nT) {
        gemm_t_body<1, 0>(sm, bid & 7, bid >> 3, F, W2h, W2l, T, 512, 1024, n,
                          NCELL * SD, SD, aF_cst, (long)NCELL * 1024, 1024, cT_cst);
    } else if (bid < nT + nR) {
        int r = bid - nT;
        gemm_t_body<0, 1>(sm, r & 31, r >> 5, P, GTtv, nullptr, Rb, 64, 4096, n,
                          NCELL * SS, SS, aP_cst, (long)NCELL * 4096, 4096, cR_cst);
    } else {
        int r = bid - nT - nR;
        gemm_t_body<0, 1>(sm, r & 63, r >> 6, P, GB2t, nullptr, R1L, 64, 8192, n,
                          NCELL * SS, SS, aP_cst, (long)LL * 8192, 8192, 0);
    }
}

// ----------------------------------------------------------------------------
// Fused per-level kernel: single pipelined split loop computing scores,
// masses AND the weighted feature combine (lagged one split), then
// normalize p, write f, u epilogue.
// ----------------------------------------------------------------------------
__device__ __forceinline__ float dot16v(uint4 v0, uint4 v1, const float* s) {
    const unsigned* u0 = (const unsigned*)&v0;
    const unsigned* u1 = (const unsigned*)&v1;
    float acc = 0.f;
    #pragma unroll
    for (int w = 0; w < 4; ++w) {
        float2 f0 = __bfloat1622float2(*(const __nv_bfloat162*)&u0[w]);
        float2 f1 = __bfloat1622float2(*(const __nv_bfloat162*)&u1[w]);
        acc += f0.x * s[2 * w]     + f0.y * s[2 * w + 1]
             + f1.x * s[8 + 2 * w] + f1.y * s[8 + 2 * w + 1];
    }
    return acc;
}

__global__ void __launch_bounds__(256) level_kernel(int ln, int n,
                                                    const float* __restrict__ bm,
                                                    int computeU) {
    int c = blockIdx.x;
    int b = c / n, i = c - b * n;
    int tid = threadIdx.x;
    int a = tid >> 2, q = tid & 3;
    int t0 = q << 4;
    __shared__ float lp[64], rp[64], us[64], red[2], sc[64];
    __shared__ float mp0[32], mp1[32], upart[256];
    float acc = 0.f;
    float2 facc = make_float2(0.f, 0.f);
    float mtot = 0.f;
    float2 bmv = *(const float2*)(bm + 2 * tid);

    // ---- prologue: stage split d=1 operands + R row ----
    float stage = 0.f;
    {
        int rLen = ln - 1;
        int soff_r = (rLen == 1) ? 64 : 0;
        if (tid < 64)
            stage = g_chart_p[(long)cellIdx(b, i, 1) * SS + 64 + tid];
        else if (tid < 128)
            stage = g_u[(long)cellIdx(b, i + 1, rLen) * SS + 64 + (tid - 64)];
        else if (tid < 192)
            stage = g_chart_p[(long)cellIdx(b, i + 1, rLen) * SS + soff_r + (tid - 128)];
    }
    uint4 rv0, rv1;
    {
        int rLen = ln - 1;
        int soff_r = (rLen == 1) ? 64 : 0;
        const __nv_bfloat16* rP = g_R1L + ((long)(b * LL + i)) * 8192
                                        + a * 128 + soff_r + t0;
        rv0 = *(const uint4*)rP;
        rv1 = *(const uint4*)(rP + 8);
    }
    float2 tl = make_float2(0.f, 0.f), tr = make_float2(0.f, 0.f);

    for (int d = 1; d < ln; ++d) {
        __syncthreads();                       // prior compute done; mp[d-2] visible
        // combine split d-1 (mass partials published last iteration)
        if (d > 1) {
            float m = mp0[d - 2] + mp1[d - 2];
            mtot += m;
            facc.x += m * fmaxf(tl.x + tr.x + bmv.x, 0.f);
            facc.y += m * fmaxf(tl.y + tr.y + bmv.y, 0.f);
        }
        if (tid < 64)       lp[tid] = stage;
        else if (tid < 128) us[tid - 64] = stage;
        else if (tid < 192) rp[tid - 128] = stage;
        __syncthreads();

        // prefetch: next split's operands + R row, and THIS split's T rows
        uint4 nv0, nv1;
        if (d + 1 < ln) {
            int dn = d + 1, rLn = ln - dn;
            int soff_rn = (rLn == 1) ? 64 : 0;
            if (tid < 64)
                stage = g_chart_p[(long)cellIdx(b, i, dn) * SS + tid];
            else if (tid < 128)
                stage = g_u[(long)cellIdx(b, i + dn, rLn) * SS + (tid - 64)];
            else if (tid < 192)
                stage = g_chart_p[(long)cellIdx(b, i + dn, rLn) * SS + soff_rn + (tid - 128)];
            const __nv_bfloat16* nP = g_Rb + (long)cellIdx(b, i + dn, rLn) * 4096
                                           + a * 64 + t0;   // dn >= 2 always Rb
            nv0 = *(const uint4*)nP;
            nv1 = *(const uint4*)(nP + 8);
        }
        {
            const float* TLp = g_T + (long)cellIdx(b, i, d) * 1024;
            const float* TRp = g_T + (long)cellIdx(b, i + d, ln - d) * 1024 + 512;
            tl = *(const float2*)(TLp + 2 * tid);
            tr = *(const float2*)(TRp + 2 * tid);
        }

        // mass_d partials (warps 0,1)
        if (tid < 64) {
            float m = lp[tid] * us[tid];
            #pragma unroll
            for (int o = 16; o; o >>= 1) m += __shfl_down_sync(0xffffffffu, m, o);
            if (tid == 0)       mp0[d - 1] = m;
            else if (tid == 32) mp1[d - 1] = m;
        }

        // score dot (R row already in registers)
        acc += dot16v(rv0, rv1, (d == 1 ? rp : lp) + t0);
        rv0 = nv0; rv1 = nv1;
    }

    int D = ln - 1;
    __syncthreads();                           // mp for split D visible
    // combine final split D
    {
        float m = mp0[D - 1] + mp1[D - 1];
        mtot += m;
        facc.x += m * fmaxf(tl.x + tr.x + bmv.x, 0.f);
        facc.y += m * fmaxf(tl.y + tr.y + bmv.y, 0.f);
    }

    // reduce scores over q
    acc += __shfl_down_sync(0xffffffffu, acc, 2);
    acc += __shfl_down_sync(0xffffffffu, acc, 1);
    if (q == 0) sc[a] = acc;
    __syncthreads();                           // sc visible
    if (tid < 64) {
        float v = sc[tid];
        #pragma unroll
        for (int o = 16; o; o >>= 1) v += __shfl_down_sync(0xffffffffu, v, o);
        if ((tid & 31) == 0) red[tid >> 5] = v;
    }
    __syncthreads();                           // red visible
    float ptot = red[0] + red[1] + EPSF;
    if (tid < 64) {
        float pv = sc[tid] / ptot;
        g_chart_p[(long)cellIdx(b, i, ln) * SS + tid] = pv;
        lp[tid] = pv;                          // normalized p for u epilogue
    }

    // write f = facc / (mtot + eps)
    float inv = 1.f / (mtot + EPSF);
    *(float2*)(g_chart_f + (long)cellIdx(b, i, ln) * SD + 2 * tid) =
        make_float2(facc.x * inv, facc.y * inv);

    // ---- u epilogue: u[j] = sum_t GsumT[0][t*128+j] * p[t], t in [0,64) ----
    if (computeU) {
        __syncthreads();                       // lp (normalized p) visible
        int j = tid & 127, h = tid >> 7;
        const float* gs = g_GsumT[0] + j;
        float partial = 0.f;
        #pragma unroll 8
        for (int t = 0; t < 32; ++t)
            partial += gs[(h * 32 + t) * 128] * lp[h * 32 + t];
        upart[tid] = partial;
        __syncthreads();
        if (tid < 128)
            g_u[(long)cellIdx(b, i, ln) * SS + tid] = upart[tid] + upart[tid + 128];
    }
}

// ----------------------------------------------------------------------------
// Root
// ----------------------------------------------------------------------------
__global__ void root_kernel(const float* __restrict__ starts, float* __restrict__ out) {
    int b = blockIdx.x, tid = threadIdx.x;  // 128 threads
    const float* p = g_chart_p + (long)cellIdx(b, 0, LL) * SS;
    float v = p[tid] * starts[tid];
    #pragma unroll
    for (int o = 16; o; o >>= 1) v += __shfl_down_sync(0xffffffffu, v, o);
    __shared__ float red[4];
    if ((tid & 31) == 0) red[tid >> 5] = v;
    __syncthreads();
    float score = red[0] + red[1] + red[2] + red[3];
    const float* f = g_chart_f + (long)cellIdx(b, 0, LL) * SD;
    for (int h = tid; h < SD; h += 128) out[b * SD + h] = f[h] * score;
}

// ----------------------------------------------------------------------------
// Host driver
// ----------------------------------------------------------------------------
extern "C" void kernel_launch(void* const* d_in, const int* in_sizes, int n_in,
                              void* d_out, int out_size) {
    const int*   word    = (const int*)  d_in[0];
    const float* emb     = (const float*)d_in[1];
    const float* preterm = (const float*)d_in[2];
    const float* G       = (const float*)d_in[3];
    const float* starts  = (const float*)d_in[4];
    const float* Wp      = (const float*)d_in[5];
    const float* bp      = (const float*)d_in[6];
    const float* Wm      = (const float*)d_in[7];
    const float* bm      = (const float*)d_in[8];
    float* out = (float*)d_out;

    float *pP, *pU, *pF, *pT, *pGsumT;
    __nv_bfloat16 *pRb, *pR1L, *pW2h, *pW2l, *pGTt, *pGB2t;
    cudaGetSymbolAddress((void**)&pP,     g_chart_p);
    cudaGetSymbolAddress((void**)&pU,     g_u);
    cudaGetSymbolAddress((void**)&pF,     g_chart_f);
    cudaGetSymbolAddress((void**)&pT,     g_T);
    cudaGetSymbolAddress((void**)&pRb,    g_Rb);
    cudaGetSymbolAddress((void**)&pR1L,   g_R1L);
    cudaGetSymbolAddress((void**)&pGsumT, g_GsumT);
    cudaGetSymbolAddress((void**)&pW2h,   g_W2hT);
    cudaGetSymbolAddress((void**)&pW2l,   g_W2lT);
    cudaGetSymbolAddress((void**)&pGTt,   g_GTt);
    cudaGetSymbolAddress((void**)&pGB2t,  g_GB2t);

    // Prep (single launch)
    prep_all<<<6208, 256>>>(G, Wm);

    // Level 1: p + u1 fused
    diag_kernel<<<BB * LL, 128>>>(word, preterm);

    {
        int rows = BB * LL;   // 2048
        // feat0 = relu(emb[word] @ Wp + bp)  (scalar GEMM, gather rows)
        dim3 gF(SD >> 6, rows >> 6);
        gemm_k<<<gF, 256>>>(emb, Wp, pF, EMB, SD, LL, word,
                            0, 0, 0,
                            (long)NCELL * SD, SD, triOff(1) * SD, bp, 0);
        // Fused T + Rb + R1L for level-1 (one launch)
        int yb = rows >> 6;                       // 32
        int blocks = yb * 8 + yb * 32 + yb * 64;  // 3328
        level_gemms<<<blocks, 256, GT_SMEM>>>(
            pP, pF, pGTt + 4096 * 64, pW2h, pW2l, pGB2t,
            pRb, pT, pR1L, LL, yb,
            triOff(1) * SS + 64, triOff(1) * 4096,
            triOff(1) * SD, triOff(1) * 1024);
    }

    // Levels 2..32
    for (int ln = 2; ln <= LL; ++ln) {
        int nn = LL - ln + 1;
        int cells = BB * nn;
        level_kernel<<<cells, 256>>>(ln, nn, bm, (ln < LL) ? 1 : 0);
        if (ln < LL) {
            int yb = nn;                          // cells/64
            int blocks = yb * 8 + yb * 32;        // T + Rb fused
            level_gemms<<<blocks, 256, GT_SMEM>>>(
                pP, pF, pGTt, pW2h, pW2l, pGB2t,
                pRb, pT, pR1L, nn, yb,
                triOff(ln) * SS, triOff(ln) * 4096,
                triOff(ln) * SD, triOff(ln) * 1024);
        }
    }

    // Root
    root_kernel<<<BB, 128>>>(starts, out);
}

// round 14
// speedup vs baseline: 4.8581x; 1.0268x over previous
#include <cuda_runtime.h>
#include <cuda_bf16.h>

// Problem constants
#define BB   64
#define LL   32
#define NT   64
#define TT   64
#define SS   128
#define VV   50000
#define EMB  512
#define SD   512
#define EPSF 1e-9f
#define NCELL 528           // L*(L+1)/2 per batch

// ----------------------------------------------------------------------------
// Persistent scratch (device globals)
// ----------------------------------------------------------------------------
__device__ float         g_chart_p[BB * NCELL * SS];    // 17 MB
__device__ float         g_u      [BB * NCELL * SS];    // 17 MB
__device__ float         g_chart_f[BB * NCELL * SD];    // 69 MB
__device__ float         g_T      [BB * NCELL * 1024];  // 138 MB  (Lt | Rt)
__device__ __nv_bfloat16 g_Rb     [BB * NCELL * 4096];  // 277 MB
__device__ __nv_bfloat16 g_R1L    [BB * LL * 8192];     // 33 MB
__device__ float         g_GsumT  [2][64 * 128];        // GsumT[v][t][s]
// Pre-transposed bf16 B matrices for tensor-core GEMMs ([N][K] layout)
__device__ __nv_bfloat16 g_W2hT[1024 * 512];            // hi split of W2^T
__device__ __nv_bfloat16 g_W2lT[1024 * 512];            // lo split
__device__ __nv_bfloat16 g_GTt [2][4096 * 64];          // GTt[v][j=a*64+s][t]
__device__ __nv_bfloat16 g_GB2t[8192 * 64];             // GB2t[j=a*128+t][s]

__host__ __device__ __forceinline__ int triOff(int len) {
    return ((len - 1) * (66 - len)) >> 1;
}
__device__ __forceinline__ int cellIdx(int b, int i, int len) {
    return b * NCELL + triOff(len) + i;
}

// ----------------------------------------------------------------------------
// Single fused prep kernel: gsum | w2t | gtt | gb2t by block range
// ----------------------------------------------------------------------------
__global__ void prep_all(const float* __restrict__ G, const float* __restrict__ Wm) {
    int bid = blockIdx.x;
    int tid = threadIdx.x;
    if (bid < 64) {
        int idx = bid * 256 + tid;                      // 2*64*128
        int v = idx >> 13, t = (idx >> 7) & 63, s = idx & 127;
        const float* gp = G + s * 128 + v * 64 + t;
        float sum = 0.f;
        #pragma unroll 8
        for (int a = 0; a < 64; ++a) sum += gp[a * 16384];
        g_GsumT[v][t * 128 + s] = sum;
    } else if (bid < 2112) {
        int idx = (bid - 64) * 256 + tid;               // 1024*512
        int j = idx >> 9, k = idx & 511;
        float w = (j < 512) ? Wm[k * 512 + j] : Wm[(512 + k) * 512 + (j - 512)];
        __nv_bfloat16 h = __float2bfloat16(w);
        g_W2hT[idx] = h;
        g_W2lT[idx] = __float2bfloat16(w - __bfloat162float(h));
    } else if (bid < 4160) {
        int idx = (bid - 2112) * 256 + tid;             // 2*4096*64
        int v = idx >> 18, r = idx & (4096 * 64 - 1);
        int j = r >> 6, t = r & 63;
        int a = j >> 6, s = j & 63;
        g_GTt[v][r] = __float2bfloat16(G[a * 16384 + s * 128 + v * 64 + t]);
    } else {
        int idx = (bid - 4160) * 256 + tid;             // 8192*64
        int j = idx >> 6, s = idx & 63;
        int a = j >> 7, t = j & 127;
        g_GB2t[idx] = __float2bfloat16(G[a * 16384 + (64 + s) * 128 + t]);
    }
}

// ----------------------------------------------------------------------------
// Level-1: preterminal distribution + u1 epilogue (fused)
// ----------------------------------------------------------------------------
__global__ void diag_kernel(const int* __restrict__ word,
                            const float* __restrict__ preterm) {
    int c = blockIdx.x;                  // b*32+i
    int tid = threadIdx.x;               // 128 threads
    int w = word[c];
    __shared__ float ps[64], red2[2];
    float v = 0.f;
    if (tid < 64) {
        v = preterm[tid * VV + w];
        float s = v;
        #pragma unroll
        for (int o = 16; o; o >>= 1) s += __shfl_down_sync(0xffffffffu, s, o);
        if ((tid & 31) == 0) red2[tid >> 5] = s;
    }
    __syncthreads();
    float tot = red2[0] + red2[1] + EPSF;
    int b = c >> 5, i = c & 31;
    long cb = (long)cellIdx(b, i, 1) * SS;
    if (tid < 64) {
        float pv = v / tot;
        g_chart_p[cb + tid]      = 0.f;
        g_chart_p[cb + 64 + tid] = pv;
        ps[tid] = pv;
    }
    __syncthreads();
    const float* gs = g_GsumT[1] + tid;
    float u = 0.f;
    #pragma unroll 8
    for (int t = 0; t < 64; ++t) u += gs[t * 128] * ps[t];
    g_u[cb + tid] = u;
}

// ----------------------------------------------------------------------------
// Scalar tiled GEMM (feat gather-GEMM only)
// ----------------------------------------------------------------------------
__global__ void __launch_bounds__(256) gemm_k(
    const float* __restrict__ A, const float* __restrict__ Bm,
    void* __restrict__ C, int K, int N, int n,
    const int* __restrict__ gidx,
    int a_bs, int a_is, int a_cst,
    long c_bs, int c_is, int c_cst,
    const float* __restrict__ bias, int obf16)
{
    __shared__ float As[16][64];
    __shared__ float Bs[16][64];
    int tid  = threadIdx.x;
    int row0 = blockIdx.y << 6, col0 = blockIdx.x << 6;

    int lr = tid >> 2, lk4 = (tid & 3) << 2;
    int r = row0 + lr;
    const float* Aptr;
    if (gidx) {
        Aptr = A + (long)gidx[r] * EMB + lk4;
    } else {
        int b = r / n, i = r - b * n;
        Aptr = A + (long)b * a_bs + (long)i * a_is + a_cst + lk4;
    }
    int bk = tid >> 4, bn4 = (tid & 15) << 2;
    const float* Bptr = Bm + (long)bk * N + col0 + bn4;

    int ty = tid >> 4, tx = tid & 15;
    float acc[4][4];
    #pragma unroll
    for (int ii = 0; ii < 4; ++ii)
        #pragma unroll
        for (int jj = 0; jj < 4; ++jj) acc[ii][jj] = 0.f;

    for (int k0 = 0; k0 < K; k0 += 16) {
        float4 av = *(const float4*)(Aptr + k0);
        float4 bv = *(const float4*)(Bptr + (long)k0 * N);
        if (k0) __syncthreads();
        As[lk4 + 0][lr] = av.x; As[lk4 + 1][lr] = av.y;
        As[lk4 + 2][lr] = av.z; As[lk4 + 3][lr] = av.w;
        *(float4*)&Bs[bk][bn4] = bv;
        __syncthreads();
        #pragma unroll
        for (int kk = 0; kk < 16; ++kk) {
            float4 af = *(const float4*)&As[kk][ty << 2];
            float4 bf = *(const float4*)&Bs[kk][tx << 2];
            float ar[4] = {af.x, af.y, af.z, af.w};
            float br[4] = {bf.x, bf.y, bf.z, bf.w};
            #pragma unroll
            for (int ii = 0; ii < 4; ++ii)
                #pragma unroll
                for (int jj = 0; jj < 4; ++jj)
                    acc[ii][jj] += ar[ii] * br[jj];
        }
    }

    int cc = col0 + (tx << 2);
    #pragma unroll
    for (int ii = 0; ii < 4; ++ii) {
        int rr = row0 + (ty << 2) + ii;
        int b = rr / n, i = rr - b * n;
        long base = (long)b * c_bs + (long)i * c_is + c_cst + cc;
        float v0 = acc[ii][0], v1 = acc[ii][1], v2 = acc[ii][2], v3 = acc[ii][3];
        if (bias) {
            v0 = fmaxf(v0 + bias[cc + 0], 0.f);
            v1 = fmaxf(v1 + bias[cc + 1], 0.f);
            v2 = fmaxf(v2 + bias[cc + 2], 0.f);
            v3 = fmaxf(v3 + bias[cc + 3], 0.f);
        }
        if (obf16) {
            __nv_bfloat162 h0 = __floats2bfloat162_rn(v0, v1);
            __nv_bfloat162 h1 = __floats2bfloat162_rn(v2, v3);
            uint2 pk = make_uint2(*(unsigned*)&h0, *(unsigned*)&h1);
            *(uint2*)((__nv_bfloat16*)C + base) = pk;
        } else {
            *(float4*)((float*)C + base) = make_float4(v0, v1, v2, v3);
        }
    }
}

// ----------------------------------------------------------------------------
// Tensor-core GEMM body with ldmatrix fragment loads
// ----------------------------------------------------------------------------
__device__ __forceinline__ void mma_bf16(float* d,
        unsigned a0, unsigned a1, unsigned a2, unsigned a3,
        unsigned b0, unsigned b1) {
    asm volatile(
        "mma.sync.aligned.m16n8k16.row.col.f32.bf16.bf16.f32 "
        "{%0,%1,%2,%3}, {%4,%5,%6,%7}, {%8,%9}, {%0,%1,%2,%3};"
        : "+f"(d[0]), "+f"(d[1]), "+f"(d[2]), "+f"(d[3])
        : "r"(a0), "r"(a1), "r"(a2), "r"(a3), "r"(b0), "r"(b1));
}

__device__ __forceinline__ void ldsm_x4(unsigned* r, unsigned addr) {
    asm volatile("ldmatrix.sync.aligned.m8n8.x4.shared.b16 {%0,%1,%2,%3}, [%4];"
        : "=r"(r[0]), "=r"(r[1]), "=r"(r[2]), "=r"(r[3]) : "r"(addr));
}

#define TPAD 40   // smem row stride in bf16 (80B = 5x16B: ldmatrix-aligned rows)
#define GT_SMEM (2 * (64 * TPAD + 64 * TPAD + 128 * TPAD + 128 * TPAD))  // 30720 B

template<int SPLIT, int OBF16>
__device__ __forceinline__ void gemm_t_body(
    char* smbase, int bx, int by,
    const float* __restrict__ A,
    const __nv_bfloat16* __restrict__ Bh,
    const __nv_bfloat16* __restrict__ Bl,
    void* __restrict__ C, int K, int N, int n,
    int a_bs, int a_is, int a_cst,
    long c_bs, int c_is, int c_cst)
{
    typedef __nv_bfloat16 bf;
    bf (*Ash)[TPAD] = (bf(*)[TPAD])(smbase);
    bf (*Asl)[TPAD] = (bf(*)[TPAD])(smbase + 5120);
    bf (*Bsh)[TPAD] = (bf(*)[TPAD])(smbase + 10240);
    bf (*Bsl)[TPAD] = (bf(*)[TPAD])(smbase + 20480);

    int tid  = threadIdx.x;
    int row0 = by << 6, col0 = bx << 7;

    int ar = tid >> 2, aq = tid & 3;
    {
        int r = row0 + ar;
        int b = r / n, i = r - b * n;
        A += (long)b * a_bs + (long)i * a_is + a_cst + aq * 8;
    }
    int brow = tid >> 1, bq = tid & 1;
    const bf* Bhp = Bh + (long)(col0 + brow) * K + bq * 16;
    const bf* Blp = SPLIT ? (Bl + (long)(col0 + brow) * K + bq * 16) : Bh;

    int w = tid >> 5, lane = tid & 31;
    int m0 = (w >> 2) << 5, n0 = (w & 3) << 5;
    int g = lane >> 2, cq = lane & 3;

    // ldmatrix shared addresses (byte, shared space)
    unsigned smA = (unsigned)__cvta_generic_to_shared(smbase);
    unsigned aRow = lane & 15, aCol = (unsigned)((lane >> 4) << 3);
    unsigned aOffH0 = smA + ((m0 + aRow) * TPAD + aCol) * 2;
    unsigned aOffH1 = aOffH0 + 16 * TPAD * 2;
    unsigned aOffL0 = aOffH0 + 5120, aOffL1 = aOffH1 + 5120;
    unsigned bRow = (unsigned)(((lane >> 4) << 3) + (lane & 7));
    unsigned bCol = (unsigned)(((lane >> 3) & 1) << 3);
    unsigned bOffH0 = smA + 10240 + ((n0 + bRow) * TPAD + bCol) * 2;
    unsigned bOffH1 = bOffH0 + 16 * TPAD * 2;
    unsigned bOffL0 = bOffH0 + 10240, bOffL1 = bOffH1 + 10240;

    float acc[2][4][4];
    #pragma unroll
    for (int mt = 0; mt < 2; ++mt)
        #pragma unroll
        for (int nt = 0; nt < 4; ++nt)
            #pragma unroll
            for (int e = 0; e < 4; ++e) acc[mt][nt][e] = 0.f;

    for (int k0 = 0; k0 < K; k0 += 32) {
        float4 av0 = *(const float4*)(A + k0);
        float4 av1 = *(const float4*)(A + k0 + 4);
        uint4 bh0 = *(const uint4*)(Bhp + k0);
        uint4 bh1 = *(const uint4*)(Bhp + k0 + 8);
        uint4 bl0, bl1;
        if (SPLIT) {
            bl0 = *(const uint4*)(Blp + k0);
            bl1 = *(const uint4*)(Blp + k0 + 8);
        }
        if (k0) __syncthreads();
        {
            float f[8] = {av0.x, av0.y, av0.z, av0.w, av1.x, av1.y, av1.z, av1.w};
            #pragma unroll
            for (int j = 0; j < 8; j += 2) {
                __nv_bfloat16 h0 = __float2bfloat16(f[j]);
                __nv_bfloat16 h1 = __float2bfloat16(f[j + 1]);
                *(__nv_bfloat162*)&Ash[ar][aq * 8 + j] = __nv_bfloat162(h0, h1);
                if (SPLIT) {
                    __nv_bfloat16 l0 = __float2bfloat16(f[j]     - __bfloat162float(h0));
                    __nv_bfloat16 l1 = __float2bfloat16(f[j + 1] - __bfloat162float(h1));
                    *(__nv_bfloat162*)&Asl[ar][aq * 8 + j] = __nv_bfloat162(l0, l1);
                }
            }
            *(uint4*)&Bsh[brow][bq * 16]     = bh0;
            *(uint4*)&Bsh[brow][bq * 16 + 8] = bh1;
            if (SPLIT) {
                *(uint4*)&Bsl[brow][bq * 16]     = bl0;
                *(uint4*)&Bsl[brow][bq * 16 + 8] = bl1;
            }
        }
        __syncthreads();

        #pragma unroll
        for (int ks = 0; ks < 2; ++ks) {
            unsigned kby = (unsigned)(ks << 5);   // 16 bf16 = 32 bytes
            unsigned ah[2][4], al[2][4];
            ldsm_x4(ah[0], aOffH0 + kby);
            ldsm_x4(ah[1], aOffH1 + kby);
            if (SPLIT) {
                ldsm_x4(al[0], aOffL0 + kby);
                ldsm_x4(al[1], aOffL1 + kby);
            }
            unsigned bhf[2][4], blf[2][4];
            ldsm_x4(bhf[0], bOffH0 + kby);
            ldsm_x4(bhf[1], bOffH1 + kby);
            if (SPLIT) {
                ldsm_x4(blf[0], bOffL0 + kby);
                ldsm_x4(blf[1], bOffL1 + kby);
            }
            #pragma unroll
            for (int nt = 0; nt < 4; ++nt) {
                int j = nt >> 1, h = (nt & 1) << 1;
                unsigned b0 = bhf[j][h], b1 = bhf[j][h + 1];
                #pragma unroll
                for (int mt = 0; mt < 2; ++mt) {
                    mma_bf16(acc[mt][nt], ah[mt][0], ah[mt][1], ah[mt][2], ah[mt][3], b0, b1);
                    if (SPLIT)
                        mma_bf16(acc[mt][nt], al[mt][0], al[mt][1], al[mt][2], al[mt][3], b0, b1);
                }
                if (SPLIT) {
                    unsigned c0 = blf[j][h], c1 = blf[j][h + 1];
                    #pragma unroll
                    for (int mt = 0; mt < 2; ++mt)
                        mma_bf16(acc[mt][nt], ah[mt][0], ah[mt][1], ah[mt][2], ah[mt][3], c0, c1);
                }
            }
        }
    }

    #pragma unroll
    for (int mt = 0; mt < 2; ++mt) {
        #pragma unroll
        for (int h2 = 0; h2 < 2; ++h2) {
            int rr = row0 + m0 + (mt << 4) + g + (h2 << 3);
            int b = rr / n, i = rr - b * n;
            long base = (long)b * c_bs + (long)i * c_is + c_cst;
            #pragma unroll
            for (int nt = 0; nt < 4; ++nt) {
                int cc = col0 + n0 + (nt << 3) + 2 * cq;
                float v0 = acc[mt][nt][h2 * 2 + 0];
                float v1 = acc[mt][nt][h2 * 2 + 1];
                if (OBF16) {
                    __nv_bfloat162 hv = __floats2bfloat162_rn(v0, v1);
                    *(unsigned*)((__nv_bfloat16*)C + base + cc) = *(unsigned*)&hv;
                } else {
                    *(float2*)((float*)C + base + cc) = make_float2(v0, v1);
                }
            }
        }
    }
}

// ----------------------------------------------------------------------------
// Fused per-level GEMM dispatcher
// ----------------------------------------------------------------------------
__global__ void __launch_bounds__(256) level_gemms(
    const float* __restrict__ P, const float* __restrict__ F,
    const __nv_bfloat16* __restrict__ GTtv,
    const __nv_bfloat16* __restrict__ W2h, const __nv_bfloat16* __restrict__ W2l,
    const __nv_bfloat16* __restrict__ GB2t,
    __nv_bfloat16* __restrict__ Rb, float* __restrict__ T,
    __nv_bfloat16* __restrict__ R1L,
    int n, int yb,
    int aP_cst, int cR_cst, int aF_cst, int cT_cst)
{
    extern __shared__ char sm[];
    int nT = yb * 8, nR = yb * 32;
    int bid = blockIdx.x;
    if (bid < nT) {
        gemm_t_body<1, 0>(sm, bid & 7, bid >> 3, F, W2h, W2l, T, 512, 1024, n,
                          NCELL * SD, SD, aF_cst, (long)NCELL * 1024, 1024, cT_cst);
    } else if (bid < nT + nR) {
        int r = bid - nT;
        gemm_t_body<0, 1>(sm, r & 31, r >> 5, P, GTtv, nullptr, Rb, 64, 4096, n,
                          NCELL * SS, SS, aP_cst, (long)NCELL * 4096, 4096, cR_cst);
    } else {
        int r = bid - nT - nR;
        gemm_t_body<0, 1>(sm, r & 63, r >> 6, P, GB2t, nullptr, R1L, 64, 8192, n,
                          NCELL * SS, SS, aP_cst, (long)LL * 8192, 8192, 0);
    }
}

// ----------------------------------------------------------------------------
// Fused per-level kernel: single pipelined split loop (2-deep prefetch of
// operands and R rows), scores + masses + lagged combine, then epilogues.
// ----------------------------------------------------------------------------
__device__ __forceinline__ float dot16v(uint4 v0, uint4 v1, const float* s) {
    const unsigned* u0 = (const unsigned*)&v0;
    const unsigned* u1 = (const unsigned*)&v1;
    float acc = 0.f;
    #pragma unroll
    for (int w = 0; w < 4; ++w) {
        float2 f0 = __bfloat1622float2(*(const __nv_bfloat162*)&u0[w]);
        float2 f1 = __bfloat1622float2(*(const __nv_bfloat162*)&u1[w]);
        acc += f0.x * s[2 * w]     + f0.y * s[2 * w + 1]
             + f1.x * s[8 + 2 * w] + f1.y * s[8 + 2 * w + 1];
    }
    return acc;
}

__global__ void __launch_bounds__(256) level_kernel(int ln, int n,
                                                    const float* __restrict__ bm,
                                                    int computeU) {
    int c = blockIdx.x;
    int b = c / n, i = c - b * n;
    int tid = threadIdx.x;
    int a = tid >> 2, q = tid & 3;
    int t0 = q << 4;
    __shared__ float lp[64], rp[64], us[64], red[2], sc[64];
    __shared__ float mp0[32], mp1[32], upart[256];
    float acc = 0.f;
    float2 facc = make_float2(0.f, 0.f);
    float mtot = 0.f;
    float2 bmv = *(const float2*)(bm + 2 * tid);

    // ---- prologue: 2-deep stage of operands + R rows (splits 1 and 2) ----
    float s_cur = 0.f, s_nxt = 0.f;
    {
        int rLen = ln - 1;
        int soff_r = (rLen == 1) ? 64 : 0;
        if (tid < 64)
            s_cur = g_chart_p[(long)cellIdx(b, i, 1) * SS + 64 + tid];
        else if (tid < 128)
            s_cur = g_u[(long)cellIdx(b, i + 1, rLen) * SS + 64 + (tid - 64)];
        else if (tid < 192)
            s_cur = g_chart_p[(long)cellIdx(b, i + 1, rLen) * SS + soff_r + (tid - 128)];
    }
    if (ln > 2) {
        int rLn = ln - 2;
        int soff_r = (rLn == 1) ? 64 : 0;
        if (tid < 64)
            s_nxt = g_chart_p[(long)cellIdx(b, i, 2) * SS + tid];
        else if (tid < 128)
            s_nxt = g_u[(long)cellIdx(b, i + 2, rLn) * SS + (tid - 64)];
        else if (tid < 192)
            s_nxt = g_chart_p[(long)cellIdx(b, i + 2, rLn) * SS + soff_r + (tid - 128)];
    }
    uint4 ra0 = make_uint4(0,0,0,0), ra1 = ra0, rb0 = ra0, rb1 = ra0;
    {
        int rLen = ln - 1;
        int soff_r = (rLen == 1) ? 64 : 0;
        const __nv_bfloat16* rP = g_R1L + ((long)(b * LL + i)) * 8192
                                        + a * 128 + soff_r + t0;
        ra0 = __ldcs((const uint4*)rP);
        ra1 = __ldcs((const uint4*)(rP + 8));
    }
    if (ln > 2) {
        const __nv_bfloat16* rP = g_Rb + (long)cellIdx(b, i + 2, ln - 2) * 4096
                                       + a * 64 + t0;
        rb0 = __ldcs((const uint4*)rP);
        rb1 = __ldcs((const uint4*)(rP + 8));
    }
    float2 tl = make_float2(0.f, 0.f), tr = make_float2(0.f, 0.f);

    for (int d = 1; d < ln; ++d) {
        __syncthreads();                       // prior compute done; mp[d-2] visible
        if (d > 1) {
            float m = mp0[d - 2] + mp1[d - 2];
            mtot += m;
            facc.x += m * fmaxf(tl.x + tr.x + bmv.x, 0.f);
            facc.y += m * fmaxf(tl.y + tr.y + bmv.y, 0.f);
        }
        if (tid < 64)       lp[tid] = s_cur;
        else if (tid < 128) us[tid - 64] = s_cur;
        else if (tid < 192) rp[tid - 128] = s_cur;
        __syncthreads();

        // advance pipeline: fetch split d+2 (operands + R row)
        s_cur = s_nxt;
        uint4 rc0 = make_uint4(0,0,0,0), rc1 = rc0;
        if (d + 2 < ln) {
            int dn = d + 2, rLn = ln - dn;
            int soff_rn = (rLn == 1) ? 64 : 0;
            if (tid < 64)
                s_nxt = g_chart_p[(long)cellIdx(b, i, dn) * SS + tid];
            else if (tid < 128)
                s_nxt = g_u[(long)cellIdx(b, i + dn, rLn) * SS + (tid - 64)];
            else if (tid < 192)
                s_nxt = g_chart_p[(long)cellIdx(b, i + dn, rLn) * SS + soff_rn + (tid - 128)];
            const __nv_bfloat16* nP = g_Rb + (long)cellIdx(b, i + dn, rLn) * 4096
                                           + a * 64 + t0;   // dn >= 3 always Rb
            rc0 = __ldcs((const uint4*)nP);
            rc1 = __ldcs((const uint4*)(nP + 8));
        }
        // T rows for this split (combined next iteration)
        {
            const float* TLp = g_T + (long)cellIdx(b, i, d) * 1024;
            const float* TRp = g_T + (long)cellIdx(b, i + d, ln - d) * 1024 + 512;
            tl = __ldcs((const float2*)(TLp + 2 * tid));
            tr = __ldcs((const float2*)(TRp + 2 * tid));
        }

        // mass_d partials (warps 0,1)
        if (tid < 64) {
            float m = lp[tid] * us[tid];
            #pragma unroll
            for (int o = 16; o; o >>= 1) m += __shfl_down_sync(0xffffffffu, m, o);
            if (tid == 0)       mp0[d - 1] = m;
            else if (tid == 32) mp1[d - 1] = m;
        }

        // score dot (R row for split d already in registers)
        acc += dot16v(ra0, ra1, (d == 1 ? rp : lp) + t0);
        ra0 = rb0; ra1 = rb1; rb0 = rc0; rb1 = rc1;
    }

    int D = ln - 1;
    __syncthreads();                           // mp for split D visible
    {
        float m = mp0[D - 1] + mp1[D - 1];
        mtot += m;
        facc.x += m * fmaxf(tl.x + tr.x + bmv.x, 0.f);
        facc.y += m * fmaxf(tl.y + tr.y + bmv.y, 0.f);
    }

    // reduce scores over q
    acc += __shfl_down_sync(0xffffffffu, acc, 2);
    acc += __shfl_down_sync(0xffffffffu, acc, 1);
    if (q == 0) sc[a] = acc;
    __syncthreads();
    if (tid < 64) {
        float v = sc[tid];
        #pragma unroll
        for (int o = 16; o; o >>= 1) v += __shfl_down_sync(0xffffffffu, v, o);
        if ((tid & 31) == 0) red[tid >> 5] = v;
    }
    __syncthreads();
    float ptot = red[0] + red[1] + EPSF;
    if (tid < 64) {
        float pv = sc[tid] / ptot;
        g_chart_p[(long)cellIdx(b, i, ln) * SS + tid] = pv;
        lp[tid] = pv;
    }

    float inv = 1.f / (mtot + EPSF);
    *(float2*)(g_chart_f + (long)cellIdx(b, i, ln) * SD + 2 * tid) =
        make_float2(facc.x * inv, facc.y * inv);

    // ---- u epilogue ----
    if (computeU) {
        __syncthreads();
        int j = tid & 127, h = tid >> 7;
        const float* gs = g_GsumT[0] + j;
        float partial = 0.f;
        #pragma unroll 8
        for (int t = 0; t < 32; ++t)
            partial += gs[(h * 32 + t) * 128] * lp[h * 32 + t];
        upart[tid] = partial;
        __syncthreads();
        if (tid < 128)
            g_u[(long)cellIdx(b, i, ln) * SS + tid] = upart[tid] + upart[tid + 128];
    }
}

// ----------------------------------------------------------------------------
// Root
// ----------------------------------------------------------------------------
__global__ void root_kernel(const float* __restrict__ starts, float* __restrict__ out) {
    int b = blockIdx.x, tid = threadIdx.x;  // 128 threads
    const float* p = g_chart_p + (long)cellIdx(b, 0, LL) * SS;
    float v = p[tid] * starts[tid];
    #pragma unroll
    for (int o = 16; o; o >>= 1) v += __shfl_down_sync(0xffffffffu, v, o);
    __shared__ float red[4];
    if ((tid & 31) == 0) red[tid >> 5] = v;
    __syncthreads();
    float score = red[0] + red[1] + red[2] + red[3];
    const float* f = g_chart_f + (long)cellIdx(b, 0, LL) * SD;
    for (int h = tid; h < SD; h += 128) out[b * SD + h] = f[h] * score;
}

// ----------------------------------------------------------------------------
// Host driver
// ----------------------------------------------------------------------------
extern "C" void kernel_launch(void* const* d_in, const int* in_sizes, int n_in,
                              void* d_out, int out_size) {
    const int*   word    = (const int*)  d_in[0];
    const float* emb     = (const float*)d_in[1];
    const float* preterm = (const float*)d_in[2];
    const float* G       = (const float*)d_in[3];
    const float* starts  = (const float*)d_in[4];
    const float* Wp      = (const float*)d_in[5];
    const float* bp      = (const float*)d_in[6];
    const float* Wm      = (const float*)d_in[7];
    const float* bm      = (const float*)d_in[8];
    float* out = (float*)d_out;

    float *pP, *pU, *pF, *pT, *pGsumT;
    __nv_bfloat16 *pRb, *pR1L, *pW2h, *pW2l, *pGTt, *pGB2t;
    cudaGetSymbolAddress((void**)&pP,     g_chart_p);
    cudaGetSymbolAddress((void**)&pU,     g_u);
    cudaGetSymbolAddress((void**)&pF,     g_chart_f);
    cudaGetSymbolAddress((void**)&pT,     g_T);
    cudaGetSymbolAddress((void**)&pRb,    g_Rb);
    cudaGetSymbolAddress((void**)&pR1L,   g_R1L);
    cudaGetSymbolAddress((void**)&pGsumT, g_GsumT);
    cudaGetSymbolAddress((void**)&pW2h,   g_W2hT);
    cudaGetSymbolAddress((void**)&pW2l,   g_W2lT);
    cudaGetSymbolAddress((void**)&pGTt,   g_GTt);
    cudaGetSymbolAddress((void**)&pGB2t,  g_GB2t);

    // Prep (single launch)
    prep_all<<<6208, 256>>>(G, Wm);

    // Level 1: p + u1 fused
    diag_kernel<<<BB * LL, 128>>>(word, preterm);

    {
        int rows = BB * LL;   // 2048
        dim3 gF(SD >> 6, rows >> 6);
        gemm_k<<<gF, 256>>>(emb, Wp, pF, EMB, SD, LL, word,
                            0, 0, 0,
                            (long)NCELL * SD, SD, triOff(1) * SD, bp, 0);
        int yb = rows >> 6;                       // 32
        int blocks = yb * 8 + yb * 32 + yb * 64;  // 3328
        level_gemms<<<blocks, 256, GT_SMEM>>>(
            pP, pF, pGTt + 4096 * 64, pW2h, pW2l, pGB2t,
            pRb, pT, pR1L, LL, yb,
            triOff(1) * SS + 64, triOff(1) * 4096,
            triOff(1) * SD, triOff(1) * 1024);
    }

    // Levels 2..32
    for (int ln = 2; ln <= LL; ++ln) {
        int nn = LL - ln + 1;
        int cells = BB * nn;
        level_kernel<<<cells, 256>>>(ln, nn, bm, (ln < LL) ? 1 : 0);
        if (ln < LL) {
            int yb = nn;
            int blocks = yb * 8 + yb * 32;
            level_gemms<<<blocks, 256, GT_SMEM>>>(
                pP, pF, pGTt, pW2h, pW2l, pGB2t,
                pRb, pT, pR1L, nn, yb,
                triOff(ln) * SS, triOff(ln) * 4096,
                triOff(ln) * SD, triOff(ln) * 1024);
        }
    }

    // Root
    root_kernel<<<BB, 128>>>(starts, out);
}